// round 1
// baseline (speedup 1.0000x reference)
#include <cuda_runtime.h>

// ---------------- problem constants ----------------
#define BB    64
#define CIN   2048
#define COUT  32
#define HH    14
#define WW    14
#define HWSZ  196
#define REP   1024
#define FEAT  (CIN*COUT)   // 65536

// fc6 tiling
#define KSPLIT 64
#define KC     (FEAT/KSPLIT)  // 1024
#define NT     128            // N columns per fc6 block

// ---------------- scratch (device globals; no allocs allowed) ----------------
__device__ float g_am[BB*COUT*HWSZ];                    // 1.6 MB
__device__ float g_feat[(size_t)BB*FEAT];               // 16.8 MB
__device__ float g_p6[(size_t)KSPLIT*BB*REP];           // 16.8 MB
__device__ float g_h6[BB*REP];                          // 0.26 MB

// ============================================================
// Kernel 1: conv 3x3, pad 1, CIN->COUT, + bias  -> g_am
// grid (7, 64): blockIdx.x = row-pair g (rows 2g,2g+1), blockIdx.y = b
// block 256 = 32 couts (o) x 8 cin-slices (s)
// ============================================================
#define TC 16   // cin per smem tile

__global__ void __launch_bounds__(256, 2)
conv_kernel(const float* __restrict__ x, const float* __restrict__ w,
            const float* __restrict__ bias)
{
    const int g   = blockIdx.x;           // 0..6
    const int b   = blockIdx.y;
    const int tid = threadIdx.x;
    const int o   = tid & 31;
    const int s   = tid >> 5;             // 0..7
    const int R0  = 2 * g;                // output rows R0, R0+1

    __shared__ float smem[7168];          // 28 KB, aliased for tiles then reduce
    float* xt = smem;                     // [TC][4][14]  = 896 floats
    float* wt = smem + 896;               // [TC][32][9]  = 4608 floats

    float acc[28];
    #pragma unroll
    for (int i = 0; i < 28; i++) acc[i] = 0.f;

    const float* xb = x + (size_t)b * CIN * HWSZ;

    for (int c0 = 0; c0 < CIN; c0 += TC) {
        __syncthreads();
        // stage x: rows R0-1..R0+2 (zero-padded), 14 cols, TC cins
        for (int t = tid; t < TC * 56; t += 256) {
            int ci = t / 56, rem = t % 56;
            int u = rem / 14, cc = rem % 14;
            int row = R0 - 1 + u;
            float v = 0.f;
            if (row >= 0 && row < HH) v = xb[(size_t)(c0 + ci) * HWSZ + row * WW + cc];
            xt[t] = v;
        }
        // stage weights: wt[ci][o][k]
        for (int t = tid; t < TC * 288; t += 256) {
            int ci = t / 288, rem = t % 288;
            int oo = rem / 9, k = rem % 9;
            wt[t] = w[(size_t)oo * (CIN * 9) + (size_t)(c0 + ci) * 9 + k];
        }
        __syncthreads();

        #pragma unroll
        for (int j = 0; j < TC / 8; j++) {
            const int ci = s + j * 8;
            float wv[9];
            #pragma unroll
            for (int k = 0; k < 9; k++) wv[k] = wt[ci * 288 + o * 9 + k];

            #pragma unroll
            for (int rr = 0; rr < 2; rr++) {
                float xr[3][14];
                #pragma unroll
                for (int dy = 0; dy < 3; dy++)
                    #pragma unroll
                    for (int cc = 0; cc < 14; cc++)
                        xr[dy][cc] = xt[ci * 56 + (rr + dy) * 14 + cc];

                #pragma unroll
                for (int cc = 0; cc < 14; cc++) {
                    float sum = 0.f;
                    #pragma unroll
                    for (int dy = 0; dy < 3; dy++) {
                        if (cc > 0)  sum += wv[dy * 3 + 0] * xr[dy][cc - 1];
                                     sum += wv[dy * 3 + 1] * xr[dy][cc];
                        if (cc < 13) sum += wv[dy * 3 + 2] * xr[dy][cc + 1];
                    }
                    acc[rr * 14 + cc] += sum;
                }
            }
        }
    }

    // block-level reduction over the 8 cin-slices (deterministic order)
    __syncthreads();
    float* rsm = smem;   // [256][28] = 7168
    #pragma unroll
    for (int i = 0; i < 28; i++) rsm[tid * 28 + i] = acc[i];
    __syncthreads();

    for (int e = tid; e < 896; e += 256) {
        int oo = e / 28, px = e % 28;
        float sum = bias[oo];
        #pragma unroll
        for (int ss = 0; ss < 8; ss++) sum += rsm[(ss * 32 + oo) * 28 + px];
        int rr = px / 14, cc = px % 14;
        g_am[((b * COUT + oo) * HH + (R0 + rr)) * WW + cc] = sum;
    }
}

// ============================================================
// Kernel 2: pooled[b,i,o] = (1/196) * sum_p x[b,i,p]*am[b,o,p] -> g_feat
// grid (128, 64): blockIdx.x = cin-tile of 16, blockIdx.y = b
// block 256 = 32 o x 8 s (each thread: cins s, s+8 of the tile)
// ============================================================
#define ETC 16

__global__ void __launch_bounds__(256)
einsum_kernel(const float* __restrict__ x)
{
    const int ct  = blockIdx.x;     // 0..127
    const int b   = blockIdx.y;
    const int tid = threadIdx.x;
    const int o   = tid & 31;
    const int s   = tid >> 5;

    __shared__ float ams[COUT * 197];      // padded rows, conflict-free
    __shared__ float xs[ETC * HWSZ];

    const float* amb = g_am + (size_t)b * COUT * HWSZ;
    for (int t = tid; t < COUT * HWSZ; t += 256) {
        int oo = t / HWSZ, p = t % HWSZ;
        ams[oo * 197 + p] = amb[t];
    }
    const float* xb = x + (size_t)b * CIN * HWSZ + (size_t)ct * ETC * HWSZ;
    for (int t = tid; t < ETC * HWSZ; t += 256) xs[t] = xb[t];
    __syncthreads();

    const float* xr0 = xs + (size_t)s * HWSZ;
    const float* xr1 = xs + (size_t)(s + 8) * HWSZ;
    const float* ar  = ams + o * 197;

    float a0 = 0.f, a1 = 0.f;
    #pragma unroll 4
    for (int p = 0; p < HWSZ; p++) {
        float av = ar[p];
        a0 += av * xr0[p];
        a1 += av * xr1[p];
    }

    const float inv = 1.f / (float)HWSZ;
    int cin = ct * ETC + s;
    g_feat[(size_t)b * FEAT + (size_t)cin * COUT + o]       = a0 * inv;
    g_feat[(size_t)b * FEAT + (size_t)(cin + 8) * COUT + o] = a1 * inv;
}

// ============================================================
// Kernel 3: fc6 partials:  p6[ks] += feat[:, ksKC:(ks+1)KC] @ w6tile^T
// grid (8, 64): blockIdx.x = N-tile (128 cols), blockIdx.y = K-split
// block 128: thread tile 8M x 8N
// ============================================================
__global__ void __launch_bounds__(128)
fc6_kernel(const float* __restrict__ w6)
{
    const int nt  = blockIdx.x;     // 0..7
    const int ks  = blockIdx.y;     // 0..63
    const int tid = threadIdx.x;
    const int ng  = tid & 15;       // n0 = 8*ng
    const int mg  = tid >> 4;       // m0 = 8*mg

    __shared__ float ft[16][64];    // k-major feat tile
    __shared__ float wts[16][NT];   // k-major w6 tile

    float acc[8][8];
    #pragma unroll
    for (int i = 0; i < 8; i++)
        #pragma unroll
        for (int j = 0; j < 8; j++) acc[i][j] = 0.f;

    const size_t kbase = (size_t)ks * KC;

    for (int kk0 = 0; kk0 < KC; kk0 += 16) {
        __syncthreads();
        {   // feat: 64 b x 16 k, each thread 8 contiguous k of one b-half
            int bb = tid >> 1;
            int kk = (tid & 1) * 8;
            const float* src = g_feat + (size_t)bb * FEAT + kbase + kk0 + kk;
            float4 v0 = *(const float4*)(src);
            float4 v1 = *(const float4*)(src + 4);
            ft[kk + 0][bb] = v0.x; ft[kk + 1][bb] = v0.y;
            ft[kk + 2][bb] = v0.z; ft[kk + 3][bb] = v0.w;
            ft[kk + 4][bb] = v1.x; ft[kk + 5][bb] = v1.y;
            ft[kk + 6][bb] = v1.z; ft[kk + 7][bb] = v1.w;
        }
        {   // w6: 128 n x 16 k, one row (16 k) per thread
            const float* src = w6 + (size_t)(nt * NT + tid) * FEAT + kbase + kk0;
            float4 v0 = *(const float4*)(src);
            float4 v1 = *(const float4*)(src + 4);
            float4 v2 = *(const float4*)(src + 8);
            float4 v3 = *(const float4*)(src + 12);
            wts[ 0][tid] = v0.x; wts[ 1][tid] = v0.y; wts[ 2][tid] = v0.z; wts[ 3][tid] = v0.w;
            wts[ 4][tid] = v1.x; wts[ 5][tid] = v1.y; wts[ 6][tid] = v1.z; wts[ 7][tid] = v1.w;
            wts[ 8][tid] = v2.x; wts[ 9][tid] = v2.y; wts[10][tid] = v2.z; wts[11][tid] = v2.w;
            wts[12][tid] = v3.x; wts[13][tid] = v3.y; wts[14][tid] = v3.z; wts[15][tid] = v3.w;
        }
        __syncthreads();

        #pragma unroll
        for (int kk = 0; kk < 16; kk++) {
            float4 f0 = *(const float4*)&ft[kk][mg * 8];
            float4 f1 = *(const float4*)&ft[kk][mg * 8 + 4];
            float4 wa = *(const float4*)&wts[kk][ng * 8];
            float4 wb = *(const float4*)&wts[kk][ng * 8 + 4];
            float fv[8] = {f0.x, f0.y, f0.z, f0.w, f1.x, f1.y, f1.z, f1.w};
            float wv[8] = {wa.x, wa.y, wa.z, wa.w, wb.x, wb.y, wb.z, wb.w};
            #pragma unroll
            for (int im = 0; im < 8; im++)
                #pragma unroll
                for (int in = 0; in < 8; in++)
                    acc[im][in] += fv[im] * wv[in];
        }
    }

    #pragma unroll
    for (int im = 0; im < 8; im++) {
        int m = mg * 8 + im;
        float* dst = g_p6 + ((size_t)ks * BB + m) * REP + nt * NT + ng * 8;
        *(float4*)(dst)     = make_float4(acc[im][0], acc[im][1], acc[im][2], acc[im][3]);
        *(float4*)(dst + 4) = make_float4(acc[im][4], acc[im][5], acc[im][6], acc[im][7]);
    }
}

// ============================================================
// Kernel 4: reduce fc6 partials + bias + relu -> g_h6
// ============================================================
__global__ void __launch_bounds__(256)
reduce6_kernel(const float* __restrict__ b6)
{
    int idx = blockIdx.x * 256 + threadIdx.x;   // 0..65535
    int b = idx >> 10, r = idx & 1023;
    float sum = b6[r];
    #pragma unroll 8
    for (int ks = 0; ks < KSPLIT; ks++)
        sum += g_p6[((size_t)ks * BB + b) * REP + r];
    g_h6[idx] = fmaxf(sum, 0.f);
}

// ============================================================
// Kernel 5: fc7 + bias + relu -> out
// grid 16 (4 batches each), block 256 (each thread: 4 r, 4 b)
// ============================================================
__global__ void __launch_bounds__(256)
fc7_kernel(const float* __restrict__ w7, const float* __restrict__ b7,
           float* __restrict__ out)
{
    const int b0  = blockIdx.x * 4;
    const int tid = threadIdx.x;

    __shared__ float hs[4][REP];
    for (int t = tid; t < 4 * REP; t += 256)
        hs[t >> 10][t & 1023] = g_h6[(size_t)(b0 + (t >> 10)) * REP + (t & 1023)];
    __syncthreads();

    #pragma unroll 1
    for (int j = 0; j < 4; j++) {
        int r = tid + 256 * j;
        const float4* wr = (const float4*)(w7 + (size_t)r * REP);
        float s0 = 0.f, s1 = 0.f, s2 = 0.f, s3 = 0.f;
        #pragma unroll 4
        for (int k4 = 0; k4 < REP / 4; k4++) {
            float4 wv = wr[k4];
            float4 h0 = *(const float4*)&hs[0][k4 * 4];
            float4 h1 = *(const float4*)&hs[1][k4 * 4];
            float4 h2 = *(const float4*)&hs[2][k4 * 4];
            float4 h3 = *(const float4*)&hs[3][k4 * 4];
            s0 += wv.x * h0.x + wv.y * h0.y + wv.z * h0.z + wv.w * h0.w;
            s1 += wv.x * h1.x + wv.y * h1.y + wv.z * h1.z + wv.w * h1.w;
            s2 += wv.x * h2.x + wv.y * h2.y + wv.z * h2.z + wv.w * h2.w;
            s3 += wv.x * h3.x + wv.y * h3.y + wv.z * h3.z + wv.w * h3.w;
        }
        float bv = b7[r];
        out[(size_t)(b0 + 0) * REP + r] = fmaxf(s0 + bv, 0.f);
        out[(size_t)(b0 + 1) * REP + r] = fmaxf(s1 + bv, 0.f);
        out[(size_t)(b0 + 2) * REP + r] = fmaxf(s2 + bv, 0.f);
        out[(size_t)(b0 + 3) * REP + r] = fmaxf(s3 + bv, 0.f);
    }
}

// ============================================================
// launch
// ============================================================
extern "C" void kernel_launch(void* const* d_in, const int* in_sizes, int n_in,
                              void* d_out, int out_size)
{
    const float* x      = (const float*)d_in[0];
    const float* conv_w = (const float*)d_in[1];
    const float* conv_b = (const float*)d_in[2];
    const float* w6     = (const float*)d_in[3];
    const float* b6     = (const float*)d_in[4];
    const float* w7     = (const float*)d_in[5];
    const float* b7     = (const float*)d_in[6];
    float* out = (float*)d_out;

    conv_kernel  <<<dim3(7, BB),   256>>>(x, conv_w, conv_b);
    einsum_kernel<<<dim3(128, BB), 256>>>(x);
    fc6_kernel   <<<dim3(8, KSPLIT), 128>>>(w6);
    reduce6_kernel<<<dim3(BB * REP / 256), 256>>>(b6);
    fc7_kernel   <<<dim3(16), 256>>>(w7, b7, out);
}

// round 3
// speedup vs baseline: 2.0265x; 2.0265x over previous
#include <cuda_runtime.h>
#include <cstdint>

// ---------------- problem constants ----------------
#define BB    64
#define CIN   2048
#define COUT  32
#define HH    14
#define WW    14
#define HWSZ  196
#define REP   1024
#define FEAT  (CIN*COUT)   // 65536

// ---------------- fc6 tiling ----------------
#define FC6_KT     32                  // K-split tiles (grid.y)
#define FC6_KPER   (FEAT/FC6_KT)       // 2048 K per CTA
#define FC6_KC     64                  // K per smem chunk
#define FC6_NCHUNK (FC6_KPER/FC6_KC)   // 32 chunks
// smem: A tile 128x68 floats, B tile 64x68 floats, double-buffered
#define A_STRIDE   68
#define A_FLOATS   (128*A_STRIDE)      // 8704
#define B_FLOATS   (64*A_STRIDE)       // 4352
#define STAGE_FLOATS (A_FLOATS+B_FLOATS)
#define FC6_SMEM   (2*STAGE_FLOATS*4)  // 104448 B

// ---------------- einsum tiling ----------------
#define EM_MT     64                   // cin rows per CTA
#define EM_KP     200                  // padded K (196 -> 200)
#define EM_SMEM   ((EM_MT*EM_KP + COUT*EM_KP)*4)   // 76800 B

// ---------------- scratch (device globals) ----------------
__device__ float g_am[BB*COUT*HWSZ];                 // 1.6 MB
__device__ float g_wt[CIN*9*COUT];                   // 2.36 MB  [ci][tap][o]
__device__ float g_feat[(size_t)BB*FEAT];            // 16.8 MB
__device__ float g_p6[(size_t)FC6_KT*REP*BB];        // 8.4 MB   [kt][r][b]
__device__ float g_h6[BB*REP];                       // 0.26 MB

// ---------------- PTX helpers ----------------
__device__ __forceinline__ uint32_t smem_u32(const void* p) {
    uint32_t a;
    asm("{ .reg .u64 t; cvta.to.shared.u64 t, %1; cvt.u32.u64 %0, t; }" : "=r"(a) : "l"(p));
    return a;
}
__device__ __forceinline__ float rna_tf32(float x) {
    uint32_t u; asm("cvt.rna.tf32.f32 %0, %1;" : "=r"(u) : "f"(x));
    return __uint_as_float(u);
}
__device__ __forceinline__ void cp_async16(uint32_t dst, const void* src) {
    asm volatile("cp.async.cg.shared.global [%0], [%1], 16;" :: "r"(dst), "l"(src) : "memory");
}
__device__ __forceinline__ void cp_commit() {
    asm volatile("cp.async.commit_group;" ::: "memory");
}
template <int N>
__device__ __forceinline__ void cp_wait() {
    asm volatile("cp.async.wait_group %0;" :: "n"(N) : "memory");
}
// D += A(16x8) * B(8x8), tf32 inputs (raw fp32 bits -> HW truncation)
__device__ __forceinline__ void mma_tf32(float* c, const uint32_t* a, const uint32_t* b) {
    asm volatile(
        "mma.sync.aligned.m16n8k8.row.col.f32.tf32.tf32.f32 "
        "{%0,%1,%2,%3}, {%4,%5,%6,%7}, {%8,%9}, {%0,%1,%2,%3};"
        : "+f"(c[0]), "+f"(c[1]), "+f"(c[2]), "+f"(c[3])
        : "r"(a[0]), "r"(a[1]), "r"(a[2]), "r"(a[3]), "r"(b[0]), "r"(b[1]));
}

// ============================================================
// Kernel 0: weight transpose  w[o][ci][k] -> g_wt[ci*9+k][o]
// ============================================================
__global__ void __launch_bounds__(256)
wtrans_kernel(const float* __restrict__ w)
{
    int idx = blockIdx.x * 256 + threadIdx.x;       // coalesced read
    if (idx >= CIN * 9 * COUT) return;
    int o = idx / (CIN * 9);
    int rem = idx - o * (CIN * 9);
    g_wt[rem * COUT + o] = w[idx];
}

// ============================================================
// Kernel 1: conv 3x3, pad 1, CIN->COUT, + bias  -> g_am
// grid (7, 64), block 256 = 32 couts x 8 cin-slices
// ============================================================
#define TC 16

__global__ void __launch_bounds__(256)
conv_kernel(const float* __restrict__ x, const float* __restrict__ bias)
{
    const int g   = blockIdx.x;
    const int b   = blockIdx.y;
    const int tid = threadIdx.x;
    const int o   = tid & 31;
    const int s   = tid >> 5;
    const int R0  = 2 * g;

    __shared__ float smem[7168];
    float* xt = smem;                     // [TC][4 rows][14 cols]

    float acc[28];
    #pragma unroll
    for (int i = 0; i < 28; i++) acc[i] = 0.f;

    const float* xb = x + (size_t)b * CIN * HWSZ;

    for (int c0 = 0; c0 < CIN; c0 += TC) {
        __syncthreads();
        for (int t = tid; t < TC * 56; t += 256) {
            int ci = t / 56, rem = t % 56;
            int u = rem / 14, cc = rem % 14;
            int row = R0 - 1 + u;
            float v = 0.f;
            if (row >= 0 && row < HH) v = xb[(size_t)(c0 + ci) * HWSZ + row * WW + cc];
            xt[t] = v;
        }
        __syncthreads();

        #pragma unroll
        for (int j = 0; j < TC / 8; j++) {
            const int ci = s + j * 8;
            const float* wp = g_wt + (size_t)(c0 + ci) * 9 * COUT + o;  // lane-coalesced
            float wv[9];
            #pragma unroll
            for (int k = 0; k < 9; k++) wv[k] = wp[k * COUT];

            const float* rbase = &xt[ci * 56];
            #pragma unroll
            for (int rr = 0; rr < 2; rr++) {
                const float* r0 = rbase + rr * 14;
                float l0 = 0.f, l1 = 0.f, l2 = 0.f;
                float c0v = r0[0], c1v = r0[14], c2v = r0[28];
                #pragma unroll
                for (int cc = 0; cc < 14; cc++) {
                    float n0 = (cc < 13) ? r0[cc + 1]  : 0.f;
                    float n1 = (cc < 13) ? r0[cc + 15] : 0.f;
                    float n2 = (cc < 13) ? r0[cc + 29] : 0.f;
                    acc[rr * 14 + cc] += wv[0]*l0 + wv[1]*c0v + wv[2]*n0
                                       + wv[3]*l1 + wv[4]*c1v + wv[5]*n1
                                       + wv[6]*l2 + wv[7]*c2v + wv[8]*n2;
                    l0 = c0v; c0v = n0;
                    l1 = c1v; c1v = n1;
                    l2 = c2v; c2v = n2;
                }
            }
        }
    }

    __syncthreads();
    float* rsm = smem;   // [256][28]
    #pragma unroll
    for (int i = 0; i < 28; i++) rsm[tid * 28 + i] = acc[i];
    __syncthreads();

    for (int e = tid; e < 896; e += 256) {
        int oo = e / 28, px = e % 28;
        float sum = bias[oo];
        #pragma unroll
        for (int ss = 0; ss < 8; ss++) sum += rsm[(ss * 32 + oo) * 28 + px];
        int rr = px / 14, cc = px % 14;
        g_am[((b * COUT + oo) * HH + (R0 + rr)) * WW + cc] = sum;
    }
}

// ============================================================
// Kernel 2: einsum via mma.sync tf32.
// pooled[b, i, o] = (1/196) * sum_p x[b,i,p] * am[b,o,p]
// Per-batch GEMM: A = x rows (M), B = am rows (N, col-major in k). K=196->200.
// grid (32, 64): 64-row cin tile, batch. block 128 (4 warps, 16 rows each).
// ============================================================
__global__ void __launch_bounds__(128)
einsum_kernel(const float* __restrict__ x)
{
    extern __shared__ float esm[];
    float* xs = esm;                 // [EM_MT][EM_KP]
    float* as_ = esm + EM_MT * EM_KP; // [COUT][EM_KP]

    const int mt  = blockIdx.x;
    const int b   = blockIdx.y;
    const int tid = threadIdx.x;
    const int wz  = tid >> 5;
    const int lane = tid & 31;
    const int qm = lane >> 2, qk = lane & 3;
    const int i0 = mt * EM_MT;

    // zero pad columns 196..199
    for (int t = tid; t < EM_MT + COUT; t += 128) {
        float* row = (t < EM_MT) ? &xs[t * EM_KP] : &as_[(t - EM_MT) * EM_KP];
        row[196] = 0.f; row[197] = 0.f; row[198] = 0.f; row[199] = 0.f;
    }

    // stage x tile (rna-converted to tf32 grid)
    const float4* xg = (const float4*)(x + (size_t)b * CIN * HWSZ + (size_t)i0 * HWSZ);
    for (int t = tid; t < EM_MT * 49; t += 128) {
        int row = t / 49, c4 = t % 49;
        float4 v = xg[row * 49 + c4];
        float* d = &xs[row * EM_KP + c4 * 4];
        d[0] = rna_tf32(v.x); d[1] = rna_tf32(v.y);
        d[2] = rna_tf32(v.z); d[3] = rna_tf32(v.w);
    }
    const float4* ag = (const float4*)(g_am + (size_t)b * COUT * HWSZ);
    for (int t = tid; t < COUT * 49; t += 128) {
        int row = t / 49, c4 = t % 49;
        float4 v = ag[row * 49 + c4];
        float* d = &as_[row * EM_KP + c4 * 4];
        d[0] = rna_tf32(v.x); d[1] = rna_tf32(v.y);
        d[2] = rna_tf32(v.z); d[3] = rna_tf32(v.w);
    }
    __syncthreads();

    const uint32_t* xu = (const uint32_t*)xs;
    const uint32_t* au = (const uint32_t*)as_;
    const int m0 = wz * 16;

    float acc[4][4];
    #pragma unroll
    for (int i = 0; i < 4; i++)
        #pragma unroll
        for (int j = 0; j < 4; j++) acc[i][j] = 0.f;

    #pragma unroll 1
    for (int ks = 0; ks < 25; ks++) {
        const int k0 = ks * 8;
        uint32_t a[4];
        a[0] = xu[(m0 + qm) * EM_KP + k0 + qk];
        a[1] = xu[(m0 + qm + 8) * EM_KP + k0 + qk];
        a[2] = xu[(m0 + qm) * EM_KP + k0 + 4 + qk];
        a[3] = xu[(m0 + qm + 8) * EM_KP + k0 + 4 + qk];
        #pragma unroll
        for (int nt = 0; nt < 4; nt++) {
            uint32_t bf[2];
            bf[0] = au[(nt * 8 + qm) * EM_KP + k0 + qk];
            bf[1] = au[(nt * 8 + qm) * EM_KP + k0 + 4 + qk];
            mma_tf32(acc[nt], a, bf);
        }
    }

    const float inv = 1.f / (float)HWSZ;
    #pragma unroll
    for (int nt = 0; nt < 4; nt++) {
        int o = nt * 8 + 2 * qk;
        int i = i0 + m0 + qm;
        float* d0 = g_feat + (size_t)b * FEAT + (size_t)i * COUT + o;
        *(float2*)d0 = make_float2(acc[nt][0] * inv, acc[nt][1] * inv);
        float* d1 = d0 + 8 * COUT;
        *(float2*)d1 = make_float2(acc[nt][2] * inv, acc[nt][3] * inv);
    }
}

// ============================================================
// Kernel 3: fc6 partials via mma.sync tf32 + cp.async pipeline.
// grid (8, 32): m-tile (128 w6 rows) x K-split. D[m=128, n=64 batch].
// ============================================================
__global__ void __launch_bounds__(128)
fc6_kernel(const float* __restrict__ w6)
{
    extern __shared__ float fsm[];
    const uint32_t sb = smem_u32(fsm);

    const int mt  = blockIdx.x;
    const int kt  = blockIdx.y;
    const int tid = threadIdx.x;
    const int wz  = tid >> 5;
    const int lane = tid & 31;
    const int qm = lane >> 2, qk = lane & 3;

    const int    mbase = mt * 128;
    const size_t kbase = (size_t)kt * FC6_KPER;

    const float* ga0 = w6 + (size_t)(mbase + tid) * FEAT + kbase;
    const int    brow = tid >> 1;
    const int    bk0  = (tid & 1) * 32;
    const float* gb0  = g_feat + (size_t)brow * FEAT + kbase + bk0;

    // cp.async one chunk into stage p
    auto prefetch = [&](int ch, int p) {
        const uint32_t abuf = sb + (uint32_t)p * (STAGE_FLOATS * 4);
        const uint32_t bbuf = abuf + A_FLOATS * 4;
        const float* ga = ga0 + (size_t)ch * FC6_KC;
        const uint32_t adst = abuf + (uint32_t)tid * (A_STRIDE * 4);
        #pragma unroll
        for (int j = 0; j < 16; j++)
            cp_async16(adst + j * 16, ga + j * 4);
        const float* gb = gb0 + (size_t)ch * FC6_KC;
        const uint32_t bdst = bbuf + (uint32_t)brow * (A_STRIDE * 4) + (uint32_t)bk0 * 4;
        #pragma unroll
        for (int j = 0; j < 8; j++)
            cp_async16(bdst + j * 16, gb + j * 4);
    };

    float acc[2][8][4];
    #pragma unroll
    for (int i = 0; i < 2; i++)
        #pragma unroll
        for (int j = 0; j < 8; j++)
            #pragma unroll
            for (int r = 0; r < 4; r++) acc[i][j][r] = 0.f;

    prefetch(0, 0);
    cp_commit();

    #pragma unroll 1
    for (int ch = 0; ch < FC6_NCHUNK; ch++) {
        if (ch + 1 < FC6_NCHUNK) {
            prefetch(ch + 1, (ch + 1) & 1);
            cp_commit();
            cp_wait<1>();
        } else {
            cp_wait<0>();
        }
        __syncthreads();

        const uint32_t* As = (const uint32_t*)fsm + (ch & 1) * STAGE_FLOATS;
        const uint32_t* Bs = As + A_FLOATS;

        #pragma unroll
        for (int ks = 0; ks < 8; ks++) {
            const int k0 = ks * 8;
            uint32_t a[2][4];
            #pragma unroll
            for (int m = 0; m < 2; m++) {
                int row = wz * 32 + m * 16 + qm;
                a[m][0] = As[row * A_STRIDE + k0 + qk];
                a[m][1] = As[(row + 8) * A_STRIDE + k0 + qk];
                a[m][2] = As[row * A_STRIDE + k0 + 4 + qk];
                a[m][3] = As[(row + 8) * A_STRIDE + k0 + 4 + qk];
            }
            #pragma unroll
            for (int nt = 0; nt < 8; nt++) {
                uint32_t bf[2];
                bf[0] = Bs[(nt * 8 + qm) * A_STRIDE + k0 + qk];
                bf[1] = Bs[(nt * 8 + qm) * A_STRIDE + k0 + 4 + qk];
                mma_tf32(acc[0][nt], a[0], bf);
                mma_tf32(acc[1][nt], a[1], bf);
            }
        }
        __syncthreads();
    }

    // partials -> g_p6[kt][r][b]
    #pragma unroll
    for (int m = 0; m < 2; m++) {
        int r = mbase + wz * 32 + m * 16 + qm;
        #pragma unroll
        for (int nt = 0; nt < 8; nt++) {
            int bcol = nt * 8 + 2 * qk;
            float* d0 = g_p6 + ((size_t)kt * REP + r) * BB + bcol;
            *(float2*)d0 = make_float2(acc[m][nt][0], acc[m][nt][1]);
            float* d1 = g_p6 + ((size_t)kt * REP + r + 8) * BB + bcol;
            *(float2*)d1 = make_float2(acc[m][nt][2], acc[m][nt][3]);
        }
    }
}

// ============================================================
// Kernel 4: reduce fc6 partials + bias + relu -> g_h6
// ============================================================
__global__ void __launch_bounds__(256)
reduce6_kernel(const float* __restrict__ b6)
{
    int idx = blockIdx.x * 256 + threadIdx.x;   // 0..65535
    int r = idx >> 6, b = idx & 63;
    float sum = b6[r];
    #pragma unroll 8
    for (int kt = 0; kt < FC6_KT; kt++)
        sum += g_p6[((size_t)kt * REP + r) * BB + b];
    g_h6[(size_t)b * REP + r] = fmaxf(sum, 0.f);
}

// ============================================================
// Kernel 5: fc7 + bias + relu -> out
// ============================================================
__global__ void __launch_bounds__(256)
fc7_kernel(const float* __restrict__ w7, const float* __restrict__ b7,
           float* __restrict__ out)
{
    const int b0  = blockIdx.x * 4;
    const int tid = threadIdx.x;

    __shared__ float hs[4][REP];
    for (int t = tid; t < 4 * REP; t += 256)
        hs[t >> 10][t & 1023] = g_h6[(size_t)(b0 + (t >> 10)) * REP + (t & 1023)];
    __syncthreads();

    #pragma unroll 1
    for (int j = 0; j < 4; j++) {
        int r = tid + 256 * j;
        const float4* wr = (const float4*)(w7 + (size_t)r * REP);
        float s0 = 0.f, s1 = 0.f, s2 = 0.f, s3 = 0.f;
        #pragma unroll 4
        for (int k4 = 0; k4 < REP / 4; k4++) {
            float4 wv = wr[k4];
            float4 h0 = *(const float4*)&hs[0][k4 * 4];
            float4 h1 = *(const float4*)&hs[1][k4 * 4];
            float4 h2 = *(const float4*)&hs[2][k4 * 4];
            float4 h3 = *(const float4*)&hs[3][k4 * 4];
            s0 += wv.x * h0.x + wv.y * h0.y + wv.z * h0.z + wv.w * h0.w;
            s1 += wv.x * h1.x + wv.y * h1.y + wv.z * h1.z + wv.w * h1.w;
            s2 += wv.x * h2.x + wv.y * h2.y + wv.z * h2.z + wv.w * h2.w;
            s3 += wv.x * h3.x + wv.y * h3.y + wv.z * h3.z + wv.w * h3.w;
        }
        float bv = b7[r];
        out[(size_t)(b0 + 0) * REP + r] = fmaxf(s0 + bv, 0.f);
        out[(size_t)(b0 + 1) * REP + r] = fmaxf(s1 + bv, 0.f);
        out[(size_t)(b0 + 2) * REP + r] = fmaxf(s2 + bv, 0.f);
        out[(size_t)(b0 + 3) * REP + r] = fmaxf(s3 + bv, 0.f);
    }
}

// ============================================================
// launch
// ============================================================
extern "C" void kernel_launch(void* const* d_in, const int* in_sizes, int n_in,
                              void* d_out, int out_size)
{
    const float* x      = (const float*)d_in[0];
    const float* conv_w = (const float*)d_in[1];
    const float* conv_b = (const float*)d_in[2];
    const float* w6     = (const float*)d_in[3];
    const float* b6     = (const float*)d_in[4];
    const float* w7     = (const float*)d_in[5];
    const float* b7     = (const float*)d_in[6];
    float* out = (float*)d_out;

    cudaFuncSetAttribute(einsum_kernel, cudaFuncAttributeMaxDynamicSharedMemorySize, EM_SMEM);
    cudaFuncSetAttribute(fc6_kernel,    cudaFuncAttributeMaxDynamicSharedMemorySize, FC6_SMEM);

    wtrans_kernel <<<dim3((CIN*9*COUT + 255)/256), 256>>>(conv_w);
    conv_kernel   <<<dim3(7, BB),        256>>>(x, conv_b);
    einsum_kernel <<<dim3(CIN/EM_MT, BB), 128, EM_SMEM>>>(x);
    fc6_kernel    <<<dim3(8, FC6_KT),    128, FC6_SMEM>>>(w6);
    reduce6_kernel<<<dim3(BB * REP / 256), 256>>>(b6);
    fc7_kernel    <<<dim3(16),           256>>>(w7, b7, out);
}

// round 5
// speedup vs baseline: 3.0500x; 1.5050x over previous
#include <cuda_runtime.h>
#include <cstdint>

// ---------------- problem constants ----------------
#define BB    64
#define CIN   2048
#define COUT  32
#define HH    14
#define WW    14
#define HWSZ  196
#define REP   1024
#define FEAT  (CIN*COUT)   // 65536

// ---------------- conv tiling ----------------
#define CV_KC      16                      // cin per chunk
#define CV_XSTR    264                     // canvas 256 + 8 pad
#define CV_WSTR    28                      // 16 k padded to 28
#define CV_XS_FL   (CV_KC*CV_XSTR)         // 4224 floats
#define CV_WS_FL   (288*CV_WSTR)           // 8064 floats (9 taps * 32 o rows)
#define CV_STAGE   (CV_XS_FL+CV_WS_FL)     // 12288 floats
#define CONV_SMEM  (2*CV_STAGE*4)          // 98304 B

// ---------------- einsum tiling ----------------
#define EM_CANV    264
#define EM_SMEM    ((64*EM_CANV + 32*EM_CANV)*4)   // 101376 B

// ---------------- fc6 tiling ----------------
#define FC6_KT     32
#define FC6_KPER   (FEAT/FC6_KT)           // 2048
#define FC6_KC     64
#define FC6_NCHUNK (FC6_KPER/FC6_KC)       // 32
#define A_STRIDE   68
#define A_FLOATS   (128*A_STRIDE)
#define B_FLOATS   (64*A_STRIDE)
#define STAGE_FLOATS (A_FLOATS+B_FLOATS)
#define FC6_SMEM   (2*STAGE_FLOATS*4)      // 104448 B

// ---------------- scratch (device globals) ----------------
__device__ float g_xp[(size_t)BB*CIN*256];           // 134 MB padded+rounded x canvas
__device__ float g_wt2[(size_t)9*COUT*CIN];          // 2.36 MB [tap][o][ci], rounded
__device__ float g_amp[(size_t)4*BB*HWSZ*COUT];      // 6.4 MB conv partials [q][b][p][o]
__device__ float g_feat[(size_t)BB*FEAT];            // 16.8 MB (tf32-rounded)
__device__ float g_p6[(size_t)FC6_KT*REP*BB];        // 8.4 MB
__device__ float g_h6[BB*REP];

// ---------------- PTX helpers ----------------
__device__ __forceinline__ uint32_t smem_u32(const void* p) {
    uint32_t a;
    asm("{ .reg .u64 t; cvta.to.shared.u64 t, %1; cvt.u32.u64 %0, t; }" : "=r"(a) : "l"(p));
    return a;
}
__device__ __forceinline__ float rna_tf32(float x) {
    uint32_t u; asm("cvt.rna.tf32.f32 %0, %1;" : "=r"(u) : "f"(x));
    return __uint_as_float(u);
}
__device__ __forceinline__ uint32_t rna_u(uint32_t bits) {
    uint32_t u; asm("cvt.rna.tf32.f32 %0, %1;" : "=r"(u) : "f"(__uint_as_float(bits)));
    return u;
}
__device__ __forceinline__ void cp_async16(uint32_t dst, const void* src) {
    asm volatile("cp.async.cg.shared.global [%0], [%1], 16;" :: "r"(dst), "l"(src) : "memory");
}
__device__ __forceinline__ void cp_commit() {
    asm volatile("cp.async.commit_group;" ::: "memory");
}
template <int N>
__device__ __forceinline__ void cp_wait() {
    asm volatile("cp.async.wait_group %0;" :: "n"(N) : "memory");
}
__device__ __forceinline__ void mma_tf32(float* c, const uint32_t* a, const uint32_t* b) {
    asm volatile(
        "mma.sync.aligned.m16n8k8.row.col.f32.tf32.tf32.f32 "
        "{%0,%1,%2,%3}, {%4,%5,%6,%7}, {%8,%9}, {%0,%1,%2,%3};"
        : "+f"(c[0]), "+f"(c[1]), "+f"(c[2]), "+f"(c[3])
        : "r"(a[0]), "r"(a[1]), "r"(a[2]), "r"(a[3]), "r"(b[0]), "r"(b[1]));
}

// ============================================================
// Kernel P1: pad + round x into 16x16 canvas  -> g_xp
// ============================================================
__global__ void __launch_bounds__(256)
xpad_kernel(const float* __restrict__ x)
{
    size_t o4 = (size_t)blockIdx.x * 256 + threadIdx.x;   // float4 index
    if (o4 >= (size_t)BB * CIN * 64) return;
    size_t bci = o4 >> 6;
    int j4 = (int)(o4 & 63);
    int v0 = j4 * 4;
    int r = v0 >> 4, c0 = v0 & 15;
    const float* src = x + bci * HWSZ;
    float v[4];
    #pragma unroll
    for (int l = 0; l < 4; l++) {
        int c = c0 + l;
        bool inb = (r >= 1 && r <= 14 && c >= 1 && c <= 14);
        v[l] = inb ? rna_tf32(src[(r - 1) * WW + (c - 1)]) : 0.f;
    }
    *(float4*)(g_xp + o4 * 4) = make_float4(v[0], v[1], v[2], v[3]);
}

// ============================================================
// Kernel P2: weight transpose+round  w[o][ci][tap] -> g_wt2[tap][o][ci]
// ============================================================
__global__ void __launch_bounds__(256)
wtrans_kernel(const float* __restrict__ w)
{
    int idx = blockIdx.x * 256 + threadIdx.x;
    if (idx >= CIN * 9 * COUT) return;
    int o   = idx / (CIN * 9);
    int rem = idx - o * (CIN * 9);
    int ci  = rem / 9;
    int tap = rem - ci * 9;
    g_wt2[((size_t)tap * COUT + o) * CIN + ci] = rna_tf32(w[idx]);
}

// ============================================================
// Kernel 1: conv via implicit GEMM (mma.sync tf32).
// grid (4, 64): cin-quarter x batch. block 256 (8 warps x 2 m-tiles of 16 px).
// ============================================================
__constant__ int TAPD[9] = {0, 1, 2, 16, 17, 18, 32, 33, 34};

__global__ void __launch_bounds__(256, 2)
conv_kernel()
{
    extern __shared__ float csm[];
    const uint32_t sb = smem_u32(csm);
    const int qx  = blockIdx.x;
    const int b   = blockIdx.y;
    const int tid = threadIdx.x;
    const int wz  = tid >> 5;
    const int lane = tid & 31;
    const int qm = lane >> 2, qk = lane & 3;

    int  ib[2][2];
    bool pv[2][2];
    #pragma unroll
    for (int t = 0; t < 2; t++) {
        int mt16 = (wz * 2 + t) * 16;
        #pragma unroll
        for (int h = 0; h < 2; h++) {
            int p = mt16 + qm + h * 8;
            bool v = p < HWSZ;
            int pr = v ? p / 14 : 0, pc = v ? p % 14 : 0;
            ib[t][h] = pr * 16 + pc;
            pv[t][h] = v;
        }
    }

    auto prefetch = [&](int ch, int pbuf) {
        const uint32_t xbuf = sb + (uint32_t)pbuf * (CV_STAGE * 4);
        const uint32_t wbuf = xbuf + CV_XS_FL * 4;
        const int cb = qx * 512 + ch * CV_KC;
        const float* xsrc = g_xp + ((size_t)b * CIN + cb) * 256;
        // x: 16 cin * 64 cp16 = 1024 transfers (256 floats per cin canvas)
        for (int q = tid; q < 1024; q += 256) {
            int ci = q >> 6, j = q & 63;
            cp_async16(xbuf + (uint32_t)(ci * CV_XSTR + j * 4) * 4, xsrc + ci * 256 + j * 4);
        }
        // w: 288 rows * 4 cp16 = 1152 transfers
        for (int q = tid; q < 1152; q += 256) {
            int row = q >> 2, j = q & 3;
            cp_async16(wbuf + (uint32_t)(row * CV_WSTR + j * 4) * 4,
                       g_wt2 + (size_t)row * CIN + cb + j * 4);
        }
    };

    float acc[2][4][4];
    #pragma unroll
    for (int t = 0; t < 2; t++)
        #pragma unroll
        for (int n = 0; n < 4; n++)
            #pragma unroll
            for (int i = 0; i < 4; i++) acc[t][n][i] = 0.f;

    prefetch(0, 0);
    cp_commit();

    #pragma unroll 1
    for (int ch = 0; ch < 32; ch++) {
        if (ch + 1 < 32) {
            prefetch(ch + 1, (ch + 1) & 1);
            cp_commit();
            cp_wait<1>();
        } else {
            cp_wait<0>();
        }
        __syncthreads();

        const uint32_t* Xs = (const uint32_t*)csm + (ch & 1) * CV_STAGE;
        const uint32_t* Ws = Xs + CV_XS_FL;

        #pragma unroll
        for (int ks = 0; ks < 2; ks++) {
            const int k0 = ks * 8;
            #pragma unroll
            for (int tap = 0; tap < 9; tap++) {
                const int d = TAPD[tap];
                uint32_t a[2][4];
                #pragma unroll
                for (int t = 0; t < 2; t++) {
                    a[t][0] = Xs[(k0 + qk) * CV_XSTR + ib[t][0] + d];
                    a[t][1] = Xs[(k0 + qk) * CV_XSTR + ib[t][1] + d];
                    a[t][2] = Xs[(k0 + qk + 4) * CV_XSTR + ib[t][0] + d];
                    a[t][3] = Xs[(k0 + qk + 4) * CV_XSTR + ib[t][1] + d];
                }
                #pragma unroll
                for (int nt = 0; nt < 4; nt++) {
                    uint32_t bf[2];
                    bf[0] = Ws[(tap * 32 + nt * 8 + qm) * CV_WSTR + k0 + qk];
                    bf[1] = Ws[(tap * 32 + nt * 8 + qm) * CV_WSTR + k0 + qk + 4];
                    mma_tf32(acc[0][nt], a[0], bf);
                    mma_tf32(acc[1][nt], a[1], bf);
                }
            }
        }
        __syncthreads();
    }

    float* dst = g_amp + ((size_t)qx * BB + b) * (HWSZ * COUT);
    #pragma unroll
    for (int t = 0; t < 2; t++) {
        #pragma unroll
        for (int h = 0; h < 2; h++) {
            if (!pv[t][h]) continue;
            int p = (wz * 2 + t) * 16 + qm + h * 8;
            #pragma unroll
            for (int nt = 0; nt < 4; nt++) {
                *(float2*)(dst + p * COUT + nt * 8 + 2 * qk) =
                    make_float2(acc[t][nt][h * 2], acc[t][nt][h * 2 + 1]);
            }
        }
    }
}

// ============================================================
// Kernel 2: einsum via mma.sync over canvas K=256 (zero pads cancel).
// grid (32, 64), block 128 (4 warps x 16 cin rows).
// ============================================================
__global__ void __launch_bounds__(128)
einsum_kernel(const float* __restrict__ bias)
{
    extern __shared__ float esm[];
    float* xs  = esm;                      // [64][264]
    float* as_ = esm + 64 * EM_CANV;       // [32][264]
    const uint32_t sb = smem_u32(esm);

    const int mt  = blockIdx.x;
    const int b   = blockIdx.y;
    const int tid = threadIdx.x;
    const int wz  = tid >> 5;
    const int lane = tid & 31;
    const int qm = lane >> 2, qk = lane & 3;
    const int i0 = mt * 64;

    // x canvas: 64 cin * 64 cp16 = 4096 transfers
    const float* xsrc = g_xp + ((size_t)b * CIN + i0) * 256;
    for (int q = tid; q < 4096; q += 128) {
        int ci = q >> 6, j = q & 63;
        cp_async16(sb + (uint32_t)(ci * EM_CANV + j * 4) * 4, xsrc + ci * 256 + j * 4);
    }
    cp_commit();

    // zero am canvas, then scatter reduced partials + bias (rounded)
    for (int t = tid; t < 32 * EM_CANV; t += 128) as_[t] = 0.f;
    __syncthreads();
    const size_t QSTR = (size_t)BB * HWSZ * COUT;
    const float* a0 = g_amp + (size_t)b * (HWSZ * COUT);
    for (int e = tid; e < HWSZ * COUT; e += 128) {
        int p = e >> 5, o = e & 31;
        float s = bias[o] + a0[e] + a0[e + QSTR] + a0[e + 2 * QSTR] + a0[e + 3 * QSTR];
        int r = p / 14, c = p % 14;
        as_[o * EM_CANV + (r + 1) * 16 + (c + 1)] = rna_tf32(s);
    }
    cp_wait<0>();
    __syncthreads();

    const uint32_t* Xu = (const uint32_t*)xs;
    const uint32_t* Au = (const uint32_t*)as_;
    const int m0 = wz * 16;

    float acc[4][4];
    #pragma unroll
    for (int i = 0; i < 4; i++)
        #pragma unroll
        for (int j = 0; j < 4; j++) acc[i][j] = 0.f;

    #pragma unroll 4
    for (int ks = 0; ks < 32; ks++) {
        const int k0 = ks * 8;
        uint32_t a[4];
        a[0] = Xu[(m0 + qm) * EM_CANV + k0 + qk];
        a[1] = Xu[(m0 + qm + 8) * EM_CANV + k0 + qk];
        a[2] = Xu[(m0 + qm) * EM_CANV + k0 + 4 + qk];
        a[3] = Xu[(m0 + qm + 8) * EM_CANV + k0 + 4 + qk];
        #pragma unroll
        for (int nt = 0; nt < 4; nt++) {
            uint32_t bf[2];
            bf[0] = Au[(nt * 8 + qm) * EM_CANV + k0 + qk];
            bf[1] = Au[(nt * 8 + qm) * EM_CANV + k0 + 4 + qk];
            mma_tf32(acc[nt], a, bf);
        }
    }

    const float inv = 1.f / (float)HWSZ;
    #pragma unroll
    for (int nt = 0; nt < 4; nt++) {
        int o = nt * 8 + 2 * qk;
        int i = i0 + m0 + qm;
        float* d0 = g_feat + (size_t)b * FEAT + (size_t)i * COUT + o;
        *(float2*)d0 = make_float2(rna_tf32(acc[nt][0] * inv), rna_tf32(acc[nt][1] * inv));
        float* d1 = d0 + 8 * COUT;
        *(float2*)d1 = make_float2(rna_tf32(acc[nt][2] * inv), rna_tf32(acc[nt][3] * inv));
    }
}

// ============================================================
// Kernel 3: fc6 partials via mma.sync tf32 + cp.async, 8 warps.
// grid (8, 32): m-tile (128 rows) x K-split. 2 CTAs/SM.
// ============================================================
__global__ void __launch_bounds__(256, 2)
fc6_kernel(const float* __restrict__ w6)
{
    extern __shared__ float fsm[];
    const uint32_t sb = smem_u32(fsm);

    const int mt  = blockIdx.x;
    const int kt  = blockIdx.y;
    const int tid = threadIdx.x;
    const int wz  = tid >> 5;
    const int lane = tid & 31;
    const int qm = lane >> 2, qk = lane & 3;

    const int    mbase = mt * 128;
    const size_t kbase = (size_t)kt * FC6_KPER;

    const int arow = tid >> 1, akoff = (tid & 1) * 32;
    const int brow = tid >> 2, bkoff = (tid & 3) * 16;
    const float* ga0 = w6 + (size_t)(mbase + arow) * FEAT + kbase + akoff;
    const float* gb0 = g_feat + (size_t)brow * FEAT + kbase + bkoff;

    auto prefetch = [&](int ch, int p) {
        const uint32_t abuf = sb + (uint32_t)p * (STAGE_FLOATS * 4);
        const uint32_t bbuf = abuf + A_FLOATS * 4;
        const float* ga = ga0 + (size_t)ch * FC6_KC;
        const uint32_t adst = abuf + (uint32_t)(arow * A_STRIDE + akoff) * 4;
        #pragma unroll
        for (int j = 0; j < 8; j++)
            cp_async16(adst + j * 16, ga + j * 4);
        const float* gb = gb0 + (size_t)ch * FC6_KC;
        const uint32_t bdst = bbuf + (uint32_t)(brow * A_STRIDE + bkoff) * 4;
        #pragma unroll
        for (int j = 0; j < 4; j++)
            cp_async16(bdst + j * 16, gb + j * 4);
    };

    float acc[8][4];
    #pragma unroll
    for (int j = 0; j < 8; j++)
        #pragma unroll
        for (int r = 0; r < 4; r++) acc[j][r] = 0.f;

    prefetch(0, 0);
    cp_commit();

    #pragma unroll 1
    for (int ch = 0; ch < FC6_NCHUNK; ch++) {
        if (ch + 1 < FC6_NCHUNK) {
            prefetch(ch + 1, (ch + 1) & 1);
            cp_commit();
            cp_wait<1>();
        } else {
            cp_wait<0>();
        }
        __syncthreads();

        const uint32_t* As = (const uint32_t*)fsm + (ch & 1) * STAGE_FLOATS;
        const uint32_t* Bs = As + A_FLOATS;
        const int m0 = wz * 16;

        #pragma unroll
        for (int ks = 0; ks < 8; ks++) {
            const int k0 = ks * 8;
            uint32_t a[4];
            a[0] = rna_u(As[(m0 + qm) * A_STRIDE + k0 + qk]);
            a[1] = rna_u(As[(m0 + qm + 8) * A_STRIDE + k0 + qk]);
            a[2] = rna_u(As[(m0 + qm) * A_STRIDE + k0 + 4 + qk]);
            a[3] = rna_u(As[(m0 + qm + 8) * A_STRIDE + k0 + 4 + qk]);
            #pragma unroll
            for (int nt = 0; nt < 8; nt++) {
                uint32_t bf[2];
                bf[0] = Bs[(nt * 8 + qm) * A_STRIDE + k0 + qk];
                bf[1] = Bs[(nt * 8 + qm) * A_STRIDE + k0 + 4 + qk];
                mma_tf32(acc[nt], a, bf);
            }
        }
        __syncthreads();
    }

    const int r = mbase + wz * 16 + qm;
    #pragma unroll
    for (int nt = 0; nt < 8; nt++) {
        int bcol = nt * 8 + 2 * qk;
        *(float2*)(g_p6 + ((size_t)kt * REP + r) * BB + bcol) =
            make_float2(acc[nt][0], acc[nt][1]);
        *(float2*)(g_p6 + ((size_t)kt * REP + r + 8) * BB + bcol) =
            make_float2(acc[nt][2], acc[nt][3]);
    }
}

// ============================================================
// Kernel 4: reduce fc6 partials + bias + relu -> g_h6
// ============================================================
__global__ void __launch_bounds__(256)
reduce6_kernel(const float* __restrict__ b6)
{
    int idx = blockIdx.x * 256 + threadIdx.x;
    int r = idx >> 6, b = idx & 63;
    float sum = b6[r];
    #pragma unroll 8
    for (int kt = 0; kt < FC6_KT; kt++)
        sum += g_p6[((size_t)kt * REP + r) * BB + b];
    g_h6[(size_t)b * REP + r] = fmaxf(sum, 0.f);
}

// ============================================================
// Kernel 5: fc7 + bias + relu -> out
// ============================================================
__global__ void __launch_bounds__(256)
fc7_kernel(const float* __restrict__ w7, const float* __restrict__ b7,
           float* __restrict__ out)
{
    const int b0  = blockIdx.x * 4;
    const int tid = threadIdx.x;

    __shared__ float hs[4][REP];
    for (int t = tid; t < 4 * REP; t += 256)
        hs[t >> 10][t & 1023] = g_h6[(size_t)(b0 + (t >> 10)) * REP + (t & 1023)];
    __syncthreads();

    #pragma unroll 1
    for (int j = 0; j < 4; j++) {
        int r = tid + 256 * j;
        const float4* wr = (const float4*)(w7 + (size_t)r * REP);
        float s0 = 0.f, s1 = 0.f, s2 = 0.f, s3 = 0.f;
        #pragma unroll 4
        for (int k4 = 0; k4 < REP / 4; k4++) {
            float4 wv = wr[k4];
            float4 h0 = *(const float4*)&hs[0][k4 * 4];
            float4 h1 = *(const float4*)&hs[1][k4 * 4];
            float4 h2 = *(const float4*)&hs[2][k4 * 4];
            float4 h3 = *(const float4*)&hs[3][k4 * 4];
            s0 += wv.x * h0.x + wv.y * h0.y + wv.z * h0.z + wv.w * h0.w;
            s1 += wv.x * h1.x + wv.y * h1.y + wv.z * h1.z + wv.w * h1.w;
            s2 += wv.x * h2.x + wv.y * h2.y + wv.z * h2.z + wv.w * h2.w;
            s3 += wv.x * h3.x + wv.y * h3.y + wv.z * h3.z + wv.w * h3.w;
        }
        float bv = b7[r];
        out[(size_t)(b0 + 0) * REP + r] = fmaxf(s0 + bv, 0.f);
        out[(size_t)(b0 + 1) * REP + r] = fmaxf(s1 + bv, 0.f);
        out[(size_t)(b0 + 2) * REP + r] = fmaxf(s2 + bv, 0.f);
        out[(size_t)(b0 + 3) * REP + r] = fmaxf(s3 + bv, 0.f);
    }
}

// ============================================================
// launch
// ============================================================
extern "C" void kernel_launch(void* const* d_in, const int* in_sizes, int n_in,
                              void* d_out, int out_size)
{
    const float* x      = (const float*)d_in[0];
    const float* conv_w = (const float*)d_in[1];
    const float* conv_b = (const float*)d_in[2];
    const float* w6     = (const float*)d_in[3];
    const float* b6     = (const float*)d_in[4];
    const float* w7     = (const float*)d_in[5];
    const float* b7     = (const float*)d_in[6];
    float* out = (float*)d_out;

    cudaFuncSetAttribute(conv_kernel,   cudaFuncAttributeMaxDynamicSharedMemorySize, CONV_SMEM);
    cudaFuncSetAttribute(einsum_kernel, cudaFuncAttributeMaxDynamicSharedMemorySize, EM_SMEM);
    cudaFuncSetAttribute(fc6_kernel,    cudaFuncAttributeMaxDynamicSharedMemorySize, FC6_SMEM);

    size_t xp4 = (size_t)BB * CIN * 64;     // float4 count
    xpad_kernel   <<<dim3((unsigned)((xp4 + 255) / 256)), 256>>>(x);
    wtrans_kernel <<<dim3((CIN * 9 * COUT + 255) / 256), 256>>>(conv_w);
    conv_kernel   <<<dim3(4, BB),  256, CONV_SMEM>>>();
    einsum_kernel <<<dim3(32, BB), 128, EM_SMEM>>>(conv_b);
    fc6_kernel    <<<dim3(8, FC6_KT), 256, FC6_SMEM>>>(w6);
    reduce6_kernel<<<dim3(BB * REP / 256), 256>>>(b6);
    fc7_kernel    <<<dim3(16), 256>>>(w7, b7, out);
}

// round 6
// speedup vs baseline: 3.6158x; 1.1855x over previous
#include <cuda_runtime.h>
#include <cstdint>

// ---------------- problem constants ----------------
#define BB    64
#define CIN   2048
#define COUT  32
#define HH    14
#define WW    14
#define HWSZ  196
#define REP   1024
#define FEAT  (CIN*COUT)   // 65536

// ---------------- conv tiling ----------------
#define CV_KC      16
#define CV_XSTR    264
#define CV_WSTR    28
#define CV_XS_FL   (CV_KC*CV_XSTR)
#define CV_WS_FL   (288*CV_WSTR)
#define CV_STAGE   (CV_XS_FL+CV_WS_FL)
#define CONV_SMEM  (2*CV_STAGE*4)          // 98304 B

// ---------------- einsum tiling ----------------
#define EM_STR     204                     // 196 + 8 pad; 204%32=12 -> conflict-free
#define EM_ROWS    96                      // 32 am + 2x32 x chunks
#define EM_SMEM    (EM_ROWS*EM_STR*4)      // 78336 B

// ---------------- fc6 tiling ----------------
#define FC6_KT     32
#define FC6_KPER   (FEAT/FC6_KT)
#define FC6_KC     64
#define FC6_NCHUNK (FC6_KPER/FC6_KC)
#define A_STRIDE   68
#define A_FLOATS   (128*A_STRIDE)
#define B_FLOATS   (64*A_STRIDE)
#define STAGE_FLOATS (A_FLOATS+B_FLOATS)
#define FC6_SMEM   (2*STAGE_FLOATS*4)      // 104448 B

// ---------------- scratch (device globals) ----------------
__device__ float g_xp[(size_t)BB*CIN*256];           // padded+rounded x canvas (conv)
__device__ float g_wt2[(size_t)9*COUT*CIN];          // [tap][o][ci], rounded
__device__ float g_amp[(size_t)4*BB*HWSZ*COUT];      // conv partials [q][b][p][o]
__device__ float g_amr[(size_t)BB*COUT*HWSZ];        // reduced am [b][o][p], rounded
__device__ float g_feat[(size_t)BB*FEAT];            // tf32-rounded
__device__ float g_p6[(size_t)FC6_KT*REP*BB];
__device__ float g_h6[BB*REP];

// ---------------- PTX helpers ----------------
__device__ __forceinline__ uint32_t smem_u32(const void* p) {
    uint32_t a;
    asm("{ .reg .u64 t; cvta.to.shared.u64 t, %1; cvt.u32.u64 %0, t; }" : "=r"(a) : "l"(p));
    return a;
}
__device__ __forceinline__ float rna_tf32(float x) {
    uint32_t u; asm("cvt.rna.tf32.f32 %0, %1;" : "=r"(u) : "f"(x));
    return __uint_as_float(u);
}
__device__ __forceinline__ uint32_t rna_u(uint32_t bits) {
    uint32_t u; asm("cvt.rna.tf32.f32 %0, %1;" : "=r"(u) : "f"(__uint_as_float(bits)));
    return u;
}
__device__ __forceinline__ void cp_async16(uint32_t dst, const void* src) {
    asm volatile("cp.async.cg.shared.global [%0], [%1], 16;" :: "r"(dst), "l"(src) : "memory");
}
__device__ __forceinline__ void cp_commit() {
    asm volatile("cp.async.commit_group;" ::: "memory");
}
template <int N>
__device__ __forceinline__ void cp_wait() {
    asm volatile("cp.async.wait_group %0;" :: "n"(N) : "memory");
}
__device__ __forceinline__ void mma_tf32(float* c, const uint32_t* a, const uint32_t* b) {
    asm volatile(
        "mma.sync.aligned.m16n8k8.row.col.f32.tf32.tf32.f32 "
        "{%0,%1,%2,%3}, {%4,%5,%6,%7}, {%8,%9}, {%0,%1,%2,%3};"
        : "+f"(c[0]), "+f"(c[1]), "+f"(c[2]), "+f"(c[3])
        : "r"(a[0]), "r"(a[1]), "r"(a[2]), "r"(a[3]), "r"(b[0]), "r"(b[1]));
}

// ============================================================
// Kernel P1: pad + round x into 16x16 canvas -> g_xp  (conv input)
// ============================================================
__global__ void __launch_bounds__(256)
xpad_kernel(const float* __restrict__ x)
{
    size_t o4 = (size_t)blockIdx.x * 256 + threadIdx.x;
    if (o4 >= (size_t)BB * CIN * 64) return;
    size_t bci = o4 >> 6;
    int j4 = (int)(o4 & 63);
    int v0 = j4 * 4;
    int r = v0 >> 4, c0 = v0 & 15;
    const float* src = x + bci * HWSZ;
    float v[4];
    #pragma unroll
    for (int l = 0; l < 4; l++) {
        int c = c0 + l;
        bool inb = (r >= 1 && r <= 14 && c >= 1 && c <= 14);
        v[l] = inb ? rna_tf32(src[(r - 1) * WW + (c - 1)]) : 0.f;
    }
    *(float4*)(g_xp + o4 * 4) = make_float4(v[0], v[1], v[2], v[3]);
}

// ============================================================
// Kernel P2: weight transpose+round  w[o][ci][tap] -> g_wt2[tap][o][ci]
// ============================================================
__global__ void __launch_bounds__(256)
wtrans_kernel(const float* __restrict__ w)
{
    int idx = blockIdx.x * 256 + threadIdx.x;
    if (idx >= CIN * 9 * COUT) return;
    int o   = idx / (CIN * 9);
    int rem = idx - o * (CIN * 9);
    int ci  = rem / 9;
    int tap = rem - ci * 9;
    g_wt2[((size_t)tap * COUT + o) * CIN + ci] = rna_tf32(w[idx]);
}

// ============================================================
// Kernel 1: conv via implicit GEMM (mma.sync tf32). (unchanged)
// ============================================================
__constant__ int TAPD[9] = {0, 1, 2, 16, 17, 18, 32, 33, 34};

__global__ void __launch_bounds__(256, 2)
conv_kernel()
{
    extern __shared__ float csm[];
    const uint32_t sb = smem_u32(csm);
    const int qx  = blockIdx.x;
    const int b   = blockIdx.y;
    const int tid = threadIdx.x;
    const int wz  = tid >> 5;
    const int lane = tid & 31;
    const int qm = lane >> 2, qk = lane & 3;

    int  ib[2][2];
    bool pv[2][2];
    #pragma unroll
    for (int t = 0; t < 2; t++) {
        int mt16 = (wz * 2 + t) * 16;
        #pragma unroll
        for (int h = 0; h < 2; h++) {
            int p = mt16 + qm + h * 8;
            bool v = p < HWSZ;
            int pr = v ? p / 14 : 0, pc = v ? p % 14 : 0;
            ib[t][h] = pr * 16 + pc;
            pv[t][h] = v;
        }
    }

    auto prefetch = [&](int ch, int pbuf) {
        const uint32_t xbuf = sb + (uint32_t)pbuf * (CV_STAGE * 4);
        const uint32_t wbuf = xbuf + CV_XS_FL * 4;
        const int cb = qx * 512 + ch * CV_KC;
        const float* xsrc = g_xp + ((size_t)b * CIN + cb) * 256;
        for (int q = tid; q < 1024; q += 256) {
            int ci = q >> 6, j = q & 63;
            cp_async16(xbuf + (uint32_t)(ci * CV_XSTR + j * 4) * 4, xsrc + ci * 256 + j * 4);
        }
        for (int q = tid; q < 1152; q += 256) {
            int row = q >> 2, j = q & 3;
            cp_async16(wbuf + (uint32_t)(row * CV_WSTR + j * 4) * 4,
                       g_wt2 + (size_t)row * CIN + cb + j * 4);
        }
    };

    float acc[2][4][4];
    #pragma unroll
    for (int t = 0; t < 2; t++)
        #pragma unroll
        for (int n = 0; n < 4; n++)
            #pragma unroll
            for (int i = 0; i < 4; i++) acc[t][n][i] = 0.f;

    prefetch(0, 0);
    cp_commit();

    #pragma unroll 1
    for (int ch = 0; ch < 32; ch++) {
        if (ch + 1 < 32) {
            prefetch(ch + 1, (ch + 1) & 1);
            cp_commit();
            cp_wait<1>();
        } else {
            cp_wait<0>();
        }
        __syncthreads();

        const uint32_t* Xs = (const uint32_t*)csm + (ch & 1) * CV_STAGE;
        const uint32_t* Ws = Xs + CV_XS_FL;

        #pragma unroll
        for (int ks = 0; ks < 2; ks++) {
            const int k0 = ks * 8;
            #pragma unroll
            for (int tap = 0; tap < 9; tap++) {
                const int d = TAPD[tap];
                uint32_t a[2][4];
                #pragma unroll
                for (int t = 0; t < 2; t++) {
                    a[t][0] = Xs[(k0 + qk) * CV_XSTR + ib[t][0] + d];
                    a[t][1] = Xs[(k0 + qk) * CV_XSTR + ib[t][1] + d];
                    a[t][2] = Xs[(k0 + qk + 4) * CV_XSTR + ib[t][0] + d];
                    a[t][3] = Xs[(k0 + qk + 4) * CV_XSTR + ib[t][1] + d];
                }
                #pragma unroll
                for (int nt = 0; nt < 4; nt++) {
                    uint32_t bf[2];
                    bf[0] = Ws[(tap * 32 + nt * 8 + qm) * CV_WSTR + k0 + qk];
                    bf[1] = Ws[(tap * 32 + nt * 8 + qm) * CV_WSTR + k0 + qk + 4];
                    mma_tf32(acc[0][nt], a[0], bf);
                    mma_tf32(acc[1][nt], a[1], bf);
                }
            }
        }
        __syncthreads();
    }

    float* dst = g_amp + ((size_t)qx * BB + b) * (HWSZ * COUT);
    #pragma unroll
    for (int t = 0; t < 2; t++) {
        #pragma unroll
        for (int h = 0; h < 2; h++) {
            if (!pv[t][h]) continue;
            int p = (wz * 2 + t) * 16 + qm + h * 8;
            #pragma unroll
            for (int nt = 0; nt < 4; nt++) {
                *(float2*)(dst + p * COUT + nt * 8 + 2 * qk) =
                    make_float2(acc[t][nt][h * 2], acc[t][nt][h * 2 + 1]);
            }
        }
    }
}

// ============================================================
// Kernel 1b: reduce conv partials + bias, round -> g_amr[b][o][p]
// ============================================================
__global__ void __launch_bounds__(256)
amred_kernel(const float* __restrict__ bias)
{
    int idx = blockIdx.x * 256 + threadIdx.x;     // b*COUT*HWSZ + o*HWSZ + p
    if (idx >= BB * COUT * HWSZ) return;
    int p   = idx % HWSZ;
    int bo  = idx / HWSZ;
    int o   = bo & 31;
    int b   = bo >> 5;
    const size_t QSTR = (size_t)BB * HWSZ * COUT;
    size_t e = (size_t)b * (HWSZ * COUT) + p * COUT + o;
    float s = bias[o] + g_amp[e] + g_amp[e + QSTR] + g_amp[e + 2 * QSTR] + g_amp[e + 3 * QSTR];
    g_amr[idx] = rna_tf32(s);
}

// ============================================================
// Kernel 2: einsum via mma.sync, cp.async double-buffered x stream.
// pooled[b,i,o] = (1/196) * sum_p x[b,i,p]*am[b,o,p]
// grid (16, 64): 128-cin tile x batch. block 256 (8 warps).
// smem rows stride EM_STR: rows 0-31 am, 32-63 xbuf0, 64-95 xbuf1.
// Warp w: mh = w>>2 (16-row half of 32-cin chunk), nt = w&3 (n8 tile).
// ============================================================
__global__ void __launch_bounds__(256, 2)
einsum_kernel(const float* __restrict__ x)
{
    extern __shared__ float esm[];
    const uint32_t sb = smem_u32(esm);

    const int mt  = blockIdx.x;
    const int b   = blockIdx.y;
    const int tid = threadIdx.x;
    const int wz  = tid >> 5;
    const int lane = tid & 31;
    const int qm = lane >> 2, qk = lane & 3;
    const int mh = wz >> 2, nt = wz & 3;
    const int i0 = mt * 128;

    // zero pad columns 196..203 of all 96 rows
    for (int t = tid; t < EM_ROWS * 8; t += 256)
        esm[(t >> 3) * EM_STR + 196 + (t & 7)] = 0.f;

    // am tile: 32 rows x 49 cp16
    const float* amsrc = g_amr + (size_t)b * (COUT * HWSZ);
    for (int q = tid; q < 32 * 49; q += 256) {
        int row = q / 49, j = q % 49;
        cp_async16(sb + (uint32_t)(row * EM_STR + j * 4) * 4, amsrc + row * HWSZ + j * 4);
    }
    const float* xsrc = x + ((size_t)b * CIN + i0) * HWSZ;

    auto prefetch_x = [&](int ch) {
        const uint32_t xbuf = sb + (uint32_t)((32 + 32 * (ch & 1)) * EM_STR) * 4;
        const float* src = xsrc + (size_t)ch * 32 * HWSZ;
        for (int q = tid; q < 32 * 49; q += 256) {
            int row = q / 49, j = q % 49;
            cp_async16(xbuf + (uint32_t)(row * EM_STR + j * 4) * 4, src + row * HWSZ + j * 4);
        }
    };

    prefetch_x(0);
    cp_commit();

    const float inv = 1.f / (float)HWSZ;
    const uint32_t* S = (const uint32_t*)esm;

    #pragma unroll 1
    for (int ch = 0; ch < 4; ch++) {
        if (ch + 1 < 4) {
            prefetch_x(ch + 1);
            cp_commit();
            cp_wait<1>();
        } else {
            cp_wait<0>();
        }
        __syncthreads();

        const int xbase = (32 + 32 * (ch & 1)) * EM_STR;
        const int arow0 = xbase + (mh * 16 + qm) * EM_STR;
        const int brow0 = (nt * 8 + qm) * EM_STR;

        float acc[4] = {0.f, 0.f, 0.f, 0.f};
        #pragma unroll 5
        for (int ks = 0; ks < 25; ks++) {
            const int k0 = ks * 8;
            uint32_t a[4], bf[2];
            a[0] = rna_u(S[arow0 + k0 + qk]);
            a[1] = rna_u(S[arow0 + 8 * EM_STR + k0 + qk]);
            a[2] = rna_u(S[arow0 + k0 + 4 + qk]);
            a[3] = rna_u(S[arow0 + 8 * EM_STR + k0 + 4 + qk]);
            bf[0] = S[brow0 + k0 + qk];
            bf[1] = S[brow0 + k0 + 4 + qk];
            mma_tf32(acc, a, bf);
        }

        // store this chunk's 16x8 tile
        int i = i0 + ch * 32 + mh * 16 + qm;
        int o = nt * 8 + 2 * qk;
        float* d0 = g_feat + (size_t)b * FEAT + (size_t)i * COUT + o;
        *(float2*)d0 = make_float2(rna_tf32(acc[0] * inv), rna_tf32(acc[1] * inv));
        float* d1 = d0 + 8 * COUT;
        *(float2*)d1 = make_float2(rna_tf32(acc[2] * inv), rna_tf32(acc[3] * inv));
        __syncthreads();
    }
}

// ============================================================
// Kernel 3: fc6 partials via mma.sync tf32 + cp.async. (unchanged)
// ============================================================
__global__ void __launch_bounds__(256, 2)
fc6_kernel(const float* __restrict__ w6)
{
    extern __shared__ float fsm[];
    const uint32_t sb = smem_u32(fsm);

    const int mt  = blockIdx.x;
    const int kt  = blockIdx.y;
    const int tid = threadIdx.x;
    const int wz  = tid >> 5;
    const int lane = tid & 31;
    const int qm = lane >> 2, qk = lane & 3;

    const int    mbase = mt * 128;
    const size_t kbase = (size_t)kt * FC6_KPER;

    const int arow = tid >> 1, akoff = (tid & 1) * 32;
    const int brow = tid >> 2, bkoff = (tid & 3) * 16;
    const float* ga0 = w6 + (size_t)(mbase + arow) * FEAT + kbase + akoff;
    const float* gb0 = g_feat + (size_t)brow * FEAT + kbase + bkoff;

    auto prefetch = [&](int ch, int p) {
        const uint32_t abuf = sb + (uint32_t)p * (STAGE_FLOATS * 4);
        const uint32_t bbuf = abuf + A_FLOATS * 4;
        const float* ga = ga0 + (size_t)ch * FC6_KC;
        const uint32_t adst = abuf + (uint32_t)(arow * A_STRIDE + akoff) * 4;
        #pragma unroll
        for (int j = 0; j < 8; j++)
            cp_async16(adst + j * 16, ga + j * 4);
        const float* gb = gb0 + (size_t)ch * FC6_KC;
        const uint32_t bdst = bbuf + (uint32_t)(brow * A_STRIDE + bkoff) * 4;
        #pragma unroll
        for (int j = 0; j < 4; j++)
            cp_async16(bdst + j * 16, gb + j * 4);
    };

    float acc[8][4];
    #pragma unroll
    for (int j = 0; j < 8; j++)
        #pragma unroll
        for (int r = 0; r < 4; r++) acc[j][r] = 0.f;

    prefetch(0, 0);
    cp_commit();

    #pragma unroll 1
    for (int ch = 0; ch < FC6_NCHUNK; ch++) {
        if (ch + 1 < FC6_NCHUNK) {
            prefetch(ch + 1, (ch + 1) & 1);
            cp_commit();
            cp_wait<1>();
        } else {
            cp_wait<0>();
        }
        __syncthreads();

        const uint32_t* As = (const uint32_t*)fsm + (ch & 1) * STAGE_FLOATS;
        const uint32_t* Bs = As + A_FLOATS;
        const int m0 = wz * 16;

        #pragma unroll
        for (int ks = 0; ks < 8; ks++) {
            const int k0 = ks * 8;
            uint32_t a[4];
            a[0] = rna_u(As[(m0 + qm) * A_STRIDE + k0 + qk]);
            a[1] = rna_u(As[(m0 + qm + 8) * A_STRIDE + k0 + qk]);
            a[2] = rna_u(As[(m0 + qm) * A_STRIDE + k0 + 4 + qk]);
            a[3] = rna_u(As[(m0 + qm + 8) * A_STRIDE + k0 + 4 + qk]);
            #pragma unroll
            for (int nt = 0; nt < 8; nt++) {
                uint32_t bf[2];
                bf[0] = Bs[(nt * 8 + qm) * A_STRIDE + k0 + qk];
                bf[1] = Bs[(nt * 8 + qm) * A_STRIDE + k0 + 4 + qk];
                mma_tf32(acc[nt], a, bf);
            }
        }
        __syncthreads();
    }

    const int r = mbase + wz * 16 + qm;
    #pragma unroll
    for (int nt = 0; nt < 8; nt++) {
        int bcol = nt * 8 + 2 * qk;
        *(float2*)(g_p6 + ((size_t)kt * REP + r) * BB + bcol) =
            make_float2(acc[nt][0], acc[nt][1]);
        *(float2*)(g_p6 + ((size_t)kt * REP + r + 8) * BB + bcol) =
            make_float2(acc[nt][2], acc[nt][3]);
    }
}

// ============================================================
// Kernel 4: reduce fc6 partials + bias + relu -> g_h6
// ============================================================
__global__ void __launch_bounds__(256)
reduce6_kernel(const float* __restrict__ b6)
{
    int idx = blockIdx.x * 256 + threadIdx.x;
    int r = idx >> 6, b = idx & 63;
    float sum = b6[r];
    #pragma unroll 8
    for (int kt = 0; kt < FC6_KT; kt++)
        sum += g_p6[((size_t)kt * REP + r) * BB + b];
    g_h6[(size_t)b * REP + r] = fmaxf(sum, 0.f);
}

// ============================================================
// Kernel 5: fc7 + bias + relu -> out
// ============================================================
__global__ void __launch_bounds__(256)
fc7_kernel(const float* __restrict__ w7, const float* __restrict__ b7,
           float* __restrict__ out)
{
    const int b0  = blockIdx.x * 4;
    const int tid = threadIdx.x;

    __shared__ float hs[4][REP];
    for (int t = tid; t < 4 * REP; t += 256)
        hs[t >> 10][t & 1023] = g_h6[(size_t)(b0 + (t >> 10)) * REP + (t & 1023)];
    __syncthreads();

    #pragma unroll 1
    for (int j = 0; j < 4; j++) {
        int r = tid + 256 * j;
        const float4* wr = (const float4*)(w7 + (size_t)r * REP);
        float s0 = 0.f, s1 = 0.f, s2 = 0.f, s3 = 0.f;
        #pragma unroll 4
        for (int k4 = 0; k4 < REP / 4; k4++) {
            float4 wv = wr[k4];
            float4 h0 = *(const float4*)&hs[0][k4 * 4];
            float4 h1 = *(const float4*)&hs[1][k4 * 4];
            float4 h2 = *(const float4*)&hs[2][k4 * 4];
            float4 h3 = *(const float4*)&hs[3][k4 * 4];
            s0 += wv.x * h0.x + wv.y * h0.y + wv.z * h0.z + wv.w * h0.w;
            s1 += wv.x * h1.x + wv.y * h1.y + wv.z * h1.z + wv.w * h1.w;
            s2 += wv.x * h2.x + wv.y * h2.y + wv.z * h2.z + wv.w * h2.w;
            s3 += wv.x * h3.x + wv.y * h3.y + wv.z * h3.z + wv.w * h3.w;
        }
        float bv = b7[r];
        out[(size_t)(b0 + 0) * REP + r] = fmaxf(s0 + bv, 0.f);
        out[(size_t)(b0 + 1) * REP + r] = fmaxf(s1 + bv, 0.f);
        out[(size_t)(b0 + 2) * REP + r] = fmaxf(s2 + bv, 0.f);
        out[(size_t)(b0 + 3) * REP + r] = fmaxf(s3 + bv, 0.f);
    }
}

// ============================================================
// launch
// ============================================================
extern "C" void kernel_launch(void* const* d_in, const int* in_sizes, int n_in,
                              void* d_out, int out_size)
{
    const float* x      = (const float*)d_in[0];
    const float* conv_w = (const float*)d_in[1];
    const float* conv_b = (const float*)d_in[2];
    const float* w6     = (const float*)d_in[3];
    const float* b6     = (const float*)d_in[4];
    const float* w7     = (const float*)d_in[5];
    const float* b7     = (const float*)d_in[6];
    float* out = (float*)d_out;

    cudaFuncSetAttribute(conv_kernel,   cudaFuncAttributeMaxDynamicSharedMemorySize, CONV_SMEM);
    cudaFuncSetAttribute(einsum_kernel, cudaFuncAttributeMaxDynamicSharedMemorySize, EM_SMEM);
    cudaFuncSetAttribute(fc6_kernel,    cudaFuncAttributeMaxDynamicSharedMemorySize, FC6_SMEM);

    size_t xp4 = (size_t)BB * CIN * 64;
    xpad_kernel   <<<dim3((unsigned)((xp4 + 255) / 256)), 256>>>(x);
    wtrans_kernel <<<dim3((CIN * 9 * COUT + 255) / 256), 256>>>(conv_w);
    conv_kernel   <<<dim3(4, BB),  256, CONV_SMEM>>>();
    amred_kernel  <<<dim3((BB * COUT * HWSZ + 255) / 256), 256>>>(conv_b);
    einsum_kernel <<<dim3(16, BB), 256, EM_SMEM>>>(x);
    fc6_kernel    <<<dim3(8, FC6_KT), 256, FC6_SMEM>>>(w6);
    reduce6_kernel<<<dim3(BB * REP / 256), 256>>>(b6);
    fc7_kernel    <<<dim3(16), 256>>>(w7, b7, out);
}

// round 7
// speedup vs baseline: 3.7175x; 1.0281x over previous
#include <cuda_runtime.h>
#include <cuda_fp16.h>
#include <cstdint>

// ---------------- problem constants ----------------
#define BB    64
#define CIN   2048
#define COUT  32
#define HH    14
#define WW    14
#define HWSZ  196
#define REP   1024
#define FEAT  (CIN*COUT)   // 65536

// ---------------- conv tiling (fp16) ----------------
#define CV_XSTR    264                     // u32 stride per k-pair row (256 pos + pad)
#define CV_WSTR    40                      // u32 stride per k-pair (32 o + pad)
#define CV_WTAP    (8*CV_WSTR)             // 320 u32 per tap
#define CV_XS_U32  (8*CV_XSTR)             // 2112
#define CV_WS_U32  (9*CV_WTAP)             // 2880
#define CV_STAGE_U32 (CV_XS_U32+CV_WS_U32) // 4992
#define CONV_SMEM  (2*CV_STAGE_U32*4)      // 39936 B

// ---------------- einsum tiling (fp16, K=208) ----------------
#define EM_STRU    108                     // u32 stride per row (104 data + pad)
#define EM_SMEM    (96*EM_STRU*4)          // 41472 B

// ---------------- fc6 tiling (tf32, unchanged) ----------------
#define FC6_KT     32
#define FC6_KPER   (FEAT/FC6_KT)
#define FC6_KC     64
#define FC6_NCHUNK (FC6_KPER/FC6_KC)
#define A_STRIDE   68
#define A_FLOATS   (128*A_STRIDE)
#define B_FLOATS   (64*A_STRIDE)
#define STAGE_FLOATS (A_FLOATS+B_FLOATS)
#define FC6_SMEM   (2*STAGE_FLOATS*4)      // 104448 B

// ---------------- scratch (device globals) ----------------
__device__ uint32_t g_xph[(size_t)BB*1024*256];   // 67 MB  conv x canvas, half2(ci even, ci odd) per pos
__device__ uint32_t g_xe[(size_t)BB*CIN*104];     // 54 MB  einsum x, half2(pos even, pos odd), K=208
__device__ uint32_t g_wt2h[128*9*8*32];           // 1.2 MB [chunk][tap][kpair][o] half2(ci even, odd)
__device__ uint32_t g_amh[BB*COUT*104];           // 0.85MB einsum am, half2 per pos pair
__device__ float g_amp[(size_t)4*BB*HWSZ*COUT];   // conv partials [q][b][p][o]
__device__ float g_feat[(size_t)BB*FEAT];         // tf32-rounded fp32
__device__ float g_p6[(size_t)FC6_KT*REP*BB];
__device__ float g_h6[BB*REP];

// ---------------- PTX helpers ----------------
__device__ __forceinline__ uint32_t smem_u32(const void* p) {
    uint32_t a;
    asm("{ .reg .u64 t; cvta.to.shared.u64 t, %1; cvt.u32.u64 %0, t; }" : "=r"(a) : "l"(p));
    return a;
}
__device__ __forceinline__ float rna_tf32(float x) {
    uint32_t u; asm("cvt.rna.tf32.f32 %0, %1;" : "=r"(u) : "f"(x));
    return __uint_as_float(u);
}
__device__ __forceinline__ uint32_t rna_u(uint32_t bits) {
    uint32_t u; asm("cvt.rna.tf32.f32 %0, %1;" : "=r"(u) : "f"(__uint_as_float(bits)));
    return u;
}
__device__ __forceinline__ uint32_t pack_h2(float a, float b) {
    __half2 h = __floats2half2_rn(a, b);
    return *(uint32_t*)&h;
}
__device__ __forceinline__ void cp_async16(uint32_t dst, const void* src) {
    asm volatile("cp.async.cg.shared.global [%0], [%1], 16;" :: "r"(dst), "l"(src) : "memory");
}
__device__ __forceinline__ void cp_commit() {
    asm volatile("cp.async.commit_group;" ::: "memory");
}
template <int N>
__device__ __forceinline__ void cp_wait() {
    asm volatile("cp.async.wait_group %0;" :: "n"(N) : "memory");
}
// tf32 m16n8k8
__device__ __forceinline__ void mma_tf32(float* c, const uint32_t* a, const uint32_t* b) {
    asm volatile(
        "mma.sync.aligned.m16n8k8.row.col.f32.tf32.tf32.f32 "
        "{%0,%1,%2,%3}, {%4,%5,%6,%7}, {%8,%9}, {%0,%1,%2,%3};"
        : "+f"(c[0]), "+f"(c[1]), "+f"(c[2]), "+f"(c[3])
        : "r"(a[0]), "r"(a[1]), "r"(a[2]), "r"(a[3]), "r"(b[0]), "r"(b[1]));
}
// fp16 m16n8k16, fp32 accum
__device__ __forceinline__ void mma_f16(float* c, const uint32_t* a, const uint32_t* b) {
    asm volatile(
        "mma.sync.aligned.m16n8k16.row.col.f32.f16.f16.f32 "
        "{%0,%1,%2,%3}, {%4,%5,%6,%7}, {%8,%9}, {%0,%1,%2,%3};"
        : "+f"(c[0]), "+f"(c[1]), "+f"(c[2]), "+f"(c[3])
        : "r"(a[0]), "r"(a[1]), "r"(a[2]), "r"(a[3]), "r"(b[0]), "r"(b[1]));
}

// ============================================================
// Kernel P1a: conv x canvas  g_xph[b][pair][pos] = half2(x(2p,pos), x(2p+1,pos))
// canvas pos = 16x16, border zero.
// ============================================================
__global__ void __launch_bounds__(256)
xpad_conv_kernel(const float* __restrict__ x)
{
    size_t idx = (size_t)blockIdx.x * 256 + threadIdx.x;
    if (idx >= (size_t)BB * 1024 * 256) return;
    int pos = (int)(idx & 255);
    size_t bp = idx >> 8;
    int pg = (int)(bp & 1023);
    int b  = (int)(bp >> 10);
    int r = pos >> 4, c = pos & 15;
    float v0 = 0.f, v1 = 0.f;
    if (r >= 1 && r <= 14 && c >= 1 && c <= 14) {
        const float* src = x + ((size_t)b * CIN + 2 * pg) * HWSZ + (r - 1) * WW + (c - 1);
        v0 = src[0];
        v1 = src[HWSZ];
    }
    g_xph[idx] = pack_h2(v0, v1);
}

// ============================================================
// Kernel P1b: einsum x  g_xe[b][ci][j] = half2(x(2j), x(2j+1)), K padded to 208
// ============================================================
__global__ void __launch_bounds__(256)
xpad_eins_kernel(const float* __restrict__ x)
{
    size_t idx = (size_t)blockIdx.x * 256 + threadIdx.x;
    if (idx >= (size_t)BB * CIN * 104) return;
    int j = (int)(idx % 104);
    size_t bc = idx / 104;
    int p0 = 2 * j, p1 = 2 * j + 1;
    const float* src = x + bc * HWSZ;
    float v0 = (p0 < HWSZ) ? src[p0] : 0.f;
    float v1 = (p1 < HWSZ) ? src[p1] : 0.f;
    g_xe[idx] = pack_h2(v0, v1);
}

// ============================================================
// Kernel P2: weights  g_wt2h[ch][tap][kp][o] = half2(w[o][ci0][tap], w[o][ci0+1][tap])
// ============================================================
__global__ void __launch_bounds__(256)
wtrans_kernel(const float* __restrict__ w)
{
    int idx = blockIdx.x * 256 + threadIdx.x;
    if (idx >= 128 * 9 * 8 * 32) return;
    int o   = idx & 31;
    int kp  = (idx >> 5) & 7;
    int tap = (idx >> 8) % 9;
    int ch  = idx / (9 * 8 * 32);
    int ci0 = ch * 16 + 2 * kp;
    float v0 = w[(size_t)o * (CIN * 9) + (size_t)ci0 * 9 + tap];
    float v1 = w[(size_t)o * (CIN * 9) + (size_t)(ci0 + 1) * 9 + tap];
    g_wt2h[idx] = pack_h2(v0, v1);
}

// ============================================================
// Kernel 1: conv via fp16 implicit GEMM (m16n8k16).
// grid (4, 64): cin-quarter x batch. block 256 (8 warps x 2 m-tiles of 16 px).
// Chunk = 16 cin = 8 k-pairs = one k16 mma step per (tap, m, n).
// ============================================================
__constant__ int TAPD[9] = {0, 1, 2, 16, 17, 18, 32, 33, 34};

__global__ void __launch_bounds__(256)
conv_kernel()
{
    extern __shared__ uint32_t csm[];
    const uint32_t sb = smem_u32(csm);
    const int qx  = blockIdx.x;
    const int b   = blockIdx.y;
    const int tid = threadIdx.x;
    const int wz  = tid >> 5;
    const int lane = tid & 31;
    const int qm = lane >> 2, qk = lane & 3;

    int  ib[2][2];
    bool pv[2][2];
    #pragma unroll
    for (int t = 0; t < 2; t++) {
        #pragma unroll
        for (int h = 0; h < 2; h++) {
            int p = (wz * 2 + t) * 16 + qm + h * 8;
            bool v = p < HWSZ;
            int pr = v ? p / 14 : 0, pc = v ? p % 14 : 0;
            ib[t][h] = pr * 16 + pc + 17;   // +17: canvas origin (1,1)-shifted tap base
            pv[t][h] = v;
        }
    }
    // TAPD[4]=17 is the center tap; ib holds (pr+1)*16+(pc+1) - 17 so base+17=center.
    // Simpler: ib = pr*16+pc, taps add 0..34 with origin at (pr,pc). (keep original)
    #pragma unroll
    for (int t = 0; t < 2; t++)
        #pragma unroll
        for (int h = 0; h < 2; h++) ib[t][h] -= 17;

    auto prefetch = [&](int ch, int pbuf) {
        const uint32_t xbuf = sb + (uint32_t)pbuf * (CV_STAGE_U32 * 4);
        const uint32_t wbuf = xbuf + CV_XS_U32 * 4;
        const int pg0 = qx * 256 + ch * 8;
        const int chg = qx * 32 + ch;
        // X: 8 kp x 64 cp16 (4 u32 each) = 512
        #pragma unroll
        for (int q = tid; q < 512; q += 256) {
            int kp = q >> 6, j = q & 63;
            cp_async16(xbuf + (uint32_t)(kp * CV_XSTR + j * 4) * 4,
                       g_xph + ((size_t)(b * 1024 + pg0 + kp)) * 256 + j * 4);
        }
        // W: 9 tap x 8 kp x 8 o-quads = 576
        for (int q = tid; q < 576; q += 256) {
            int tap = q / 64;
            int kp  = (q >> 3) & 7;
            int oq  = q & 7;
            cp_async16(wbuf + (uint32_t)(tap * CV_WTAP + kp * CV_WSTR + oq * 4) * 4,
                       g_wt2h + ((size_t)(chg * 9 + tap) * 8 + kp) * 32 + oq * 4);
        }
    };

    float acc[2][4][4];
    #pragma unroll
    for (int t = 0; t < 2; t++)
        #pragma unroll
        for (int n = 0; n < 4; n++)
            #pragma unroll
            for (int i = 0; i < 4; i++) acc[t][n][i] = 0.f;

    prefetch(0, 0);
    cp_commit();

    #pragma unroll 1
    for (int ch = 0; ch < 32; ch++) {
        if (ch + 1 < 32) {
            prefetch(ch + 1, (ch + 1) & 1);
            cp_commit();
            cp_wait<1>();
        } else {
            cp_wait<0>();
        }
        __syncthreads();

        const uint32_t* Xs = csm + (ch & 1) * CV_STAGE_U32;
        const uint32_t* Ws = Xs + CV_XS_U32;

        #pragma unroll
        for (int tap = 0; tap < 9; tap++) {
            const int d = TAPD[tap];
            uint32_t a[2][4];
            #pragma unroll
            for (int t = 0; t < 2; t++) {
                a[t][0] = Xs[qk * CV_XSTR + ib[t][0] + d];
                a[t][1] = Xs[qk * CV_XSTR + ib[t][1] + d];
                a[t][2] = Xs[(qk + 4) * CV_XSTR + ib[t][0] + d];
                a[t][3] = Xs[(qk + 4) * CV_XSTR + ib[t][1] + d];
            }
            #pragma unroll
            for (int nt = 0; nt < 4; nt++) {
                uint32_t bf[2];
                bf[0] = Ws[tap * CV_WTAP + qk * CV_WSTR + nt * 8 + qm];
                bf[1] = Ws[tap * CV_WTAP + (qk + 4) * CV_WSTR + nt * 8 + qm];
                mma_f16(acc[0][nt], a[0], bf);
                mma_f16(acc[1][nt], a[1], bf);
            }
        }
        __syncthreads();
    }

    float* dst = g_amp + ((size_t)qx * BB + b) * (HWSZ * COUT);
    #pragma unroll
    for (int t = 0; t < 2; t++) {
        #pragma unroll
        for (int h = 0; h < 2; h++) {
            if (!pv[t][h]) continue;
            int p = (wz * 2 + t) * 16 + qm + h * 8;
            #pragma unroll
            for (int nt = 0; nt < 4; nt++) {
                *(float2*)(dst + p * COUT + nt * 8 + 2 * qk) =
                    make_float2(acc[t][nt][h * 2], acc[t][nt][h * 2 + 1]);
            }
        }
    }
}

// ============================================================
// Kernel 1b: reduce conv partials + bias -> g_amh[b][o][104] half2 (K=208, zero-padded)
// ============================================================
__global__ void __launch_bounds__(256)
amred_kernel(const float* __restrict__ bias)
{
    int idx = blockIdx.x * 256 + threadIdx.x;
    if (idx >= BB * COUT * 104) return;
    int j  = idx % 104;
    int bo = idx / 104;
    int o  = bo & 31;
    int b  = bo >> 5;
    const size_t QSTR = (size_t)BB * HWSZ * COUT;
    float s[2] = {0.f, 0.f};
    #pragma unroll
    for (int l = 0; l < 2; l++) {
        int p = 2 * j + l;
        if (p < HWSZ) {
            size_t e = (size_t)b * (HWSZ * COUT) + (size_t)p * COUT + o;
            s[l] = bias[o] + g_amp[e] + g_amp[e + QSTR] + g_amp[e + 2 * QSTR] + g_amp[e + 3 * QSTR];
        }
    }
    g_amh[idx] = pack_h2(s[0], s[1]);
}

// ============================================================
// Kernel 2: einsum via fp16 mma (m16n8k16), K=208 over positions.
// grid (16, 64): 128-cin tile x batch. block 256 (8 warps: mh=wz>>2, nt=wz&3).
// smem rows (u32 stride EM_STRU): 0-31 am, 32-63 xbuf0, 64-95 xbuf1.
// ============================================================
__global__ void __launch_bounds__(256)
einsum_kernel()
{
    extern __shared__ uint32_t esm[];
    const uint32_t sb = smem_u32(esm);

    const int mt  = blockIdx.x;
    const int b   = blockIdx.y;
    const int tid = threadIdx.x;
    const int wz  = tid >> 5;
    const int lane = tid & 31;
    const int qm = lane >> 2, qk = lane & 3;
    const int mh = wz >> 2, nt = wz & 3;
    const int i0 = mt * 128;

    // am tile: 32 rows x 26 cp16
    for (int q = tid; q < 832; q += 256) {
        int row = q / 26, j = q % 26;
        cp_async16(sb + (uint32_t)(row * EM_STRU + j * 4) * 4,
                   g_amh + (size_t)(b * COUT + row) * 104 + j * 4);
    }

    auto prefetch_x = [&](int ch) {
        const uint32_t xbuf = sb + (uint32_t)((32 + 32 * (ch & 1)) * EM_STRU) * 4;
        for (int q = tid; q < 832; q += 256) {
            int row = q / 26, j = q % 26;
            cp_async16(xbuf + (uint32_t)(row * EM_STRU + j * 4) * 4,
                       g_xe + (size_t)(b * CIN + i0 + ch * 32 + row) * 104 + j * 4);
        }
    };

    prefetch_x(0);
    cp_commit();

    const float inv = 1.f / (float)HWSZ;

    #pragma unroll 1
    for (int ch = 0; ch < 4; ch++) {
        if (ch + 1 < 4) {
            prefetch_x(ch + 1);
            cp_commit();
            cp_wait<1>();
        } else {
            cp_wait<0>();
        }
        __syncthreads();

        const int arow0 = (32 + 32 * (ch & 1) + mh * 16 + qm) * EM_STRU;
        const int brow0 = (nt * 8 + qm) * EM_STRU;

        float acc[4] = {0.f, 0.f, 0.f, 0.f};
        #pragma unroll
        for (int ks = 0; ks < 13; ks++) {
            const int k0 = ks * 8;
            uint32_t a[4], bf[2];
            a[0] = esm[arow0 + k0 + qk];
            a[1] = esm[arow0 + 8 * EM_STRU + k0 + qk];
            a[2] = esm[arow0 + k0 + 4 + qk];
            a[3] = esm[arow0 + 8 * EM_STRU + k0 + 4 + qk];
            bf[0] = esm[brow0 + k0 + qk];
            bf[1] = esm[brow0 + k0 + 4 + qk];
            mma_f16(acc, a, bf);
        }

        int i = i0 + ch * 32 + mh * 16 + qm;
        int o = nt * 8 + 2 * qk;
        float* d0 = g_feat + (size_t)b * FEAT + (size_t)i * COUT + o;
        *(float2*)d0 = make_float2(rna_tf32(acc[0] * inv), rna_tf32(acc[1] * inv));
        float* d1 = d0 + 8 * COUT;
        *(float2*)d1 = make_float2(rna_tf32(acc[2] * inv), rna_tf32(acc[3] * inv));
        __syncthreads();
    }
}

// ============================================================
// Kernel 3: fc6 partials via mma.sync tf32 + cp.async. (unchanged, known-good)
// ============================================================
__global__ void __launch_bounds__(256, 2)
fc6_kernel(const float* __restrict__ w6)
{
    extern __shared__ float fsm[];
    const uint32_t sb = smem_u32(fsm);

    const int mt  = blockIdx.x;
    const int kt  = blockIdx.y;
    const int tid = threadIdx.x;
    const int wz  = tid >> 5;
    const int lane = tid & 31;
    const int qm = lane >> 2, qk = lane & 3;

    const int    mbase = mt * 128;
    const size_t kbase = (size_t)kt * FC6_KPER;

    const int arow = tid >> 1, akoff = (tid & 1) * 32;
    const int brow = tid >> 2, bkoff = (tid & 3) * 16;
    const float* ga0 = w6 + (size_t)(mbase + arow) * FEAT + kbase + akoff;
    const float* gb0 = g_feat + (size_t)brow * FEAT + kbase + bkoff;

    auto prefetch = [&](int ch, int p) {
        const uint32_t abuf = sb + (uint32_t)p * (STAGE_FLOATS * 4);
        const uint32_t bbuf = abuf + A_FLOATS * 4;
        const float* ga = ga0 + (size_t)ch * FC6_KC;
        const uint32_t adst = abuf + (uint32_t)(arow * A_STRIDE + akoff) * 4;
        #pragma unroll
        for (int j = 0; j < 8; j++)
            cp_async16(adst + j * 16, ga + j * 4);
        const float* gb = gb0 + (size_t)ch * FC6_KC;
        const uint32_t bdst = bbuf + (uint32_t)(brow * A_STRIDE + bkoff) * 4;
        #pragma unroll
        for (int j = 0; j < 4; j++)
            cp_async16(bdst + j * 16, gb + j * 4);
    };

    float acc[8][4];
    #pragma unroll
    for (int j = 0; j < 8; j++)
        #pragma unroll
        for (int r = 0; r < 4; r++) acc[j][r] = 0.f;

    prefetch(0, 0);
    cp_commit();

    #pragma unroll 1
    for (int ch = 0; ch < FC6_NCHUNK; ch++) {
        if (ch + 1 < FC6_NCHUNK) {
            prefetch(ch + 1, (ch + 1) & 1);
            cp_commit();
            cp_wait<1>();
        } else {
            cp_wait<0>();
        }
        __syncthreads();

        const uint32_t* As = (const uint32_t*)fsm + (ch & 1) * STAGE_FLOATS;
        const uint32_t* Bs = As + A_FLOATS;
        const int m0 = wz * 16;

        #pragma unroll
        for (int ks = 0; ks < 8; ks++) {
            const int k0 = ks * 8;
            uint32_t a[4];
            a[0] = rna_u(As[(m0 + qm) * A_STRIDE + k0 + qk]);
            a[1] = rna_u(As[(m0 + qm + 8) * A_STRIDE + k0 + qk]);
            a[2] = rna_u(As[(m0 + qm) * A_STRIDE + k0 + 4 + qk]);
            a[3] = rna_u(As[(m0 + qm + 8) * A_STRIDE + k0 + 4 + qk]);
            #pragma unroll
            for (int nt = 0; nt < 8; nt++) {
                uint32_t bf[2];
                bf[0] = Bs[(nt * 8 + qm) * A_STRIDE + k0 + qk];
                bf[1] = Bs[(nt * 8 + qm) * A_STRIDE + k0 + 4 + qk];
                mma_tf32(acc[nt], a, bf);
            }
        }
        __syncthreads();
    }

    const int r = mbase + wz * 16 + qm;
    #pragma unroll
    for (int nt = 0; nt < 8; nt++) {
        int bcol = nt * 8 + 2 * qk;
        *(float2*)(g_p6 + ((size_t)kt * REP + r) * BB + bcol) =
            make_float2(acc[nt][0], acc[nt][1]);
        *(float2*)(g_p6 + ((size_t)kt * REP + r + 8) * BB + bcol) =
            make_float2(acc[nt][2], acc[nt][3]);
    }
}

// ============================================================
// Kernel 4: reduce fc6 partials + bias + relu -> g_h6
// ============================================================
__global__ void __launch_bounds__(256)
reduce6_kernel(const float* __restrict__ b6)
{
    int idx = blockIdx.x * 256 + threadIdx.x;
    int r = idx >> 6, b = idx & 63;
    float sum = b6[r];
    #pragma unroll 8
    for (int kt = 0; kt < FC6_KT; kt++)
        sum += g_p6[((size_t)kt * REP + r) * BB + b];
    g_h6[(size_t)b * REP + r] = fmaxf(sum, 0.f);
}

// ============================================================
// Kernel 5: fc7 + bias + relu -> out
// ============================================================
__global__ void __launch_bounds__(256)
fc7_kernel(const float* __restrict__ w7, const float* __restrict__ b7,
           float* __restrict__ out)
{
    const int b0  = blockIdx.x * 4;
    const int tid = threadIdx.x;

    __shared__ float hs[4][REP];
    for (int t = tid; t < 4 * REP; t += 256)
        hs[t >> 10][t & 1023] = g_h6[(size_t)(b0 + (t >> 10)) * REP + (t & 1023)];
    __syncthreads();

    #pragma unroll 1
    for (int j = 0; j < 4; j++) {
        int r = tid + 256 * j;
        const float4* wr = (const float4*)(w7 + (size_t)r * REP);
        float s0 = 0.f, s1 = 0.f, s2 = 0.f, s3 = 0.f;
        #pragma unroll 4
        for (int k4 = 0; k4 < REP / 4; k4++) {
            float4 wv = wr[k4];
            float4 h0 = *(const float4*)&hs[0][k4 * 4];
            float4 h1 = *(const float4*)&hs[1][k4 * 4];
            float4 h2 = *(const float4*)&hs[2][k4 * 4];
            float4 h3 = *(const float4*)&hs[3][k4 * 4];
            s0 += wv.x * h0.x + wv.y * h0.y + wv.z * h0.z + wv.w * h0.w;
            s1 += wv.x * h1.x + wv.y * h1.y + wv.z * h1.z + wv.w * h1.w;
            s2 += wv.x * h2.x + wv.y * h2.y + wv.z * h2.z + wv.w * h2.w;
            s3 += wv.x * h3.x + wv.y * h3.y + wv.z * h3.z + wv.w * h3.w;
        }
        float bv = b7[r];
        out[(size_t)(b0 + 0) * REP + r] = fmaxf(s0 + bv, 0.f);
        out[(size_t)(b0 + 1) * REP + r] = fmaxf(s1 + bv, 0.f);
        out[(size_t)(b0 + 2) * REP + r] = fmaxf(s2 + bv, 0.f);
        out[(size_t)(b0 + 3) * REP + r] = fmaxf(s3 + bv, 0.f);
    }
}

// ============================================================
// launch (conv at index 3 for ncu)
// ============================================================
extern "C" void kernel_launch(void* const* d_in, const int* in_sizes, int n_in,
                              void* d_out, int out_size)
{
    const float* x      = (const float*)d_in[0];
    const float* conv_w = (const float*)d_in[1];
    const float* conv_b = (const float*)d_in[2];
    const float* w6     = (const float*)d_in[3];
    const float* b6     = (const float*)d_in[4];
    const float* w7     = (const float*)d_in[5];
    const float* b7     = (const float*)d_in[6];
    float* out = (float*)d_out;

    cudaFuncSetAttribute(conv_kernel,   cudaFuncAttributeMaxDynamicSharedMemorySize, CONV_SMEM);
    cudaFuncSetAttribute(einsum_kernel, cudaFuncAttributeMaxDynamicSharedMemorySize, EM_SMEM);
    cudaFuncSetAttribute(fc6_kernel,    cudaFuncAttributeMaxDynamicSharedMemorySize, FC6_SMEM);

    size_t nxc = (size_t)BB * 1024 * 256;
    size_t nxe = (size_t)BB * CIN * 104;
    xpad_conv_kernel<<<dim3((unsigned)((nxc + 255) / 256)), 256>>>(x);
    xpad_eins_kernel<<<dim3((unsigned)((nxe + 255) / 256)), 256>>>(x);
    wtrans_kernel   <<<dim3((128 * 9 * 8 * 32 + 255) / 256), 256>>>(conv_w);
    conv_kernel     <<<dim3(4, BB),  256, CONV_SMEM>>>();
    amred_kernel    <<<dim3((BB * COUT * 104 + 255) / 256), 256>>>(conv_b);
    einsum_kernel   <<<dim3(16, BB), 256, EM_SMEM>>>();
    fc6_kernel      <<<dim3(8, FC6_KT), 256, FC6_SMEM>>>(w6);
    reduce6_kernel  <<<dim3(BB * REP / 256), 256>>>(b6);
    fc7_kernel      <<<dim3(16), 256>>>(w7, b7, out);
}

// round 8
// speedup vs baseline: 5.2413x; 1.4099x over previous
#include <cuda_runtime.h>
#include <cuda_fp16.h>
#include <cstdint>

// ---------------- problem constants ----------------
#define BB    64
#define CIN   2048
#define COUT  32
#define HH    14
#define WW    14
#define HWSZ  196
#define REP   1024
#define FEAT  (CIN*COUT)   // 65536

// ---------------- conv tiling (fp16) ----------------
#define CV_XSTR    264
#define CV_WSTR    40
#define CV_WTAP    (8*CV_WSTR)
#define CV_XS_U32  (8*CV_XSTR)
#define CV_WS_U32  (9*CV_WTAP)
#define CV_STAGE_U32 (CV_XS_U32+CV_WS_U32)
#define CONV_SMEM  (2*CV_STAGE_U32*4)      // 39936 B

// ---------------- einsum tiling (fp16, K=208) ----------------
#define EM_STRU    108
#define EM_SMEM    (96*EM_STRU*4)          // 41472 B

// ---------------- fc6 tiling (tf32, 4-stage pipeline) ----------------
#define FC6_KT     32
#define FC6_KPER   (FEAT/FC6_KT)           // 2048
#define FC6_KC     32                      // K floats per chunk
#define FC6_NCHUNK (FC6_KPER/FC6_KC)       // 64
#define F6_STR     36                      // float stride (32 + 4 pad)
#define A_FLOATS   (128*F6_STR)            // 4608
#define B_FLOATS   (64*F6_STR)             // 2304
#define STAGE_FLOATS (A_FLOATS+B_FLOATS)   // 6912
#define FC6_NSTG   4
#define FC6_SMEM   (FC6_NSTG*STAGE_FLOATS*4)  // 110592 B

// ---------------- scratch (device globals) ----------------
__device__ uint32_t g_xph[(size_t)BB*1024*256];   // conv x canvas half2
__device__ uint32_t g_xe[(size_t)BB*CIN*104];     // einsum x half2, K=208
__device__ uint32_t g_wt2h[128*9*8*32];           // conv weights half2
__device__ uint32_t g_amh[BB*COUT*104];           // einsum am half2
__device__ float g_amp[(size_t)4*BB*HWSZ*COUT];   // conv partials
__device__ float g_feat[(size_t)BB*FEAT];         // tf32-rounded fp32
__device__ float g_p6[(size_t)FC6_KT*REP*BB];
__device__ float g_h6[BB*REP];

// ---------------- PTX helpers ----------------
__device__ __forceinline__ uint32_t smem_u32(const void* p) {
    uint32_t a;
    asm("{ .reg .u64 t; cvta.to.shared.u64 t, %1; cvt.u32.u64 %0, t; }" : "=r"(a) : "l"(p));
    return a;
}
__device__ __forceinline__ float rna_tf32(float x) {
    uint32_t u; asm("cvt.rna.tf32.f32 %0, %1;" : "=r"(u) : "f"(x));
    return __uint_as_float(u);
}
__device__ __forceinline__ uint32_t rna_u(uint32_t bits) {
    uint32_t u; asm("cvt.rna.tf32.f32 %0, %1;" : "=r"(u) : "f"(__uint_as_float(bits)));
    return u;
}
__device__ __forceinline__ uint32_t pack_h2(float a, float b) {
    __half2 h = __floats2half2_rn(a, b);
    return *(uint32_t*)&h;
}
__device__ __forceinline__ void cp_async16(uint32_t dst, const void* src) {
    asm volatile("cp.async.cg.shared.global [%0], [%1], 16;" :: "r"(dst), "l"(src) : "memory");
}
__device__ __forceinline__ void cp_commit() {
    asm volatile("cp.async.commit_group;" ::: "memory");
}
template <int N>
__device__ __forceinline__ void cp_wait() {
    asm volatile("cp.async.wait_group %0;" :: "n"(N) : "memory");
}
__device__ __forceinline__ void mma_tf32(float* c, const uint32_t* a, const uint32_t* b) {
    asm volatile(
        "mma.sync.aligned.m16n8k8.row.col.f32.tf32.tf32.f32 "
        "{%0,%1,%2,%3}, {%4,%5,%6,%7}, {%8,%9}, {%0,%1,%2,%3};"
        : "+f"(c[0]), "+f"(c[1]), "+f"(c[2]), "+f"(c[3])
        : "r"(a[0]), "r"(a[1]), "r"(a[2]), "r"(a[3]), "r"(b[0]), "r"(b[1]));
}
__device__ __forceinline__ void mma_f16(float* c, const uint32_t* a, const uint32_t* b) {
    asm volatile(
        "mma.sync.aligned.m16n8k16.row.col.f32.f16.f16.f32 "
        "{%0,%1,%2,%3}, {%4,%5,%6,%7}, {%8,%9}, {%0,%1,%2,%3};"
        : "+f"(c[0]), "+f"(c[1]), "+f"(c[2]), "+f"(c[3])
        : "r"(a[0]), "r"(a[1]), "r"(a[2]), "r"(a[3]), "r"(b[0]), "r"(b[1]));
}

// ============================================================
// Kernel P1a: conv x canvas (half2 cin-pairs, 16x16, border zero)
// ============================================================
__global__ void __launch_bounds__(256)
xpad_conv_kernel(const float* __restrict__ x)
{
    size_t idx = (size_t)blockIdx.x * 256 + threadIdx.x;
    if (idx >= (size_t)BB * 1024 * 256) return;
    int pos = (int)(idx & 255);
    size_t bp = idx >> 8;
    int pg = (int)(bp & 1023);
    int b  = (int)(bp >> 10);
    int r = pos >> 4, c = pos & 15;
    float v0 = 0.f, v1 = 0.f;
    if (r >= 1 && r <= 14 && c >= 1 && c <= 14) {
        const float* src = x + ((size_t)b * CIN + 2 * pg) * HWSZ + (r - 1) * WW + (c - 1);
        v0 = src[0];
        v1 = src[HWSZ];
    }
    g_xph[idx] = pack_h2(v0, v1);
}

// ============================================================
// Kernel P1b: einsum x (half2 pos-pairs, K padded to 208)
// ============================================================
__global__ void __launch_bounds__(256)
xpad_eins_kernel(const float* __restrict__ x)
{
    size_t idx = (size_t)blockIdx.x * 256 + threadIdx.x;
    if (idx >= (size_t)BB * CIN * 104) return;
    int j = (int)(idx % 104);
    size_t bc = idx / 104;
    int p0 = 2 * j, p1 = 2 * j + 1;
    const float* src = x + bc * HWSZ;
    float v0 = (p0 < HWSZ) ? src[p0] : 0.f;
    float v1 = (p1 < HWSZ) ? src[p1] : 0.f;
    g_xe[idx] = pack_h2(v0, v1);
}

// ============================================================
// Kernel P2: conv weights half2
// ============================================================
__global__ void __launch_bounds__(256)
wtrans_kernel(const float* __restrict__ w)
{
    int idx = blockIdx.x * 256 + threadIdx.x;
    if (idx >= 128 * 9 * 8 * 32) return;
    int o   = idx & 31;
    int kp  = (idx >> 5) & 7;
    int tap = (idx >> 8) % 9;
    int ch  = idx / (9 * 8 * 32);
    int ci0 = ch * 16 + 2 * kp;
    float v0 = w[(size_t)o * (CIN * 9) + (size_t)ci0 * 9 + tap];
    float v1 = w[(size_t)o * (CIN * 9) + (size_t)(ci0 + 1) * 9 + tap];
    g_wt2h[idx] = pack_h2(v0, v1);
}

// ============================================================
// Kernel 1: conv via fp16 implicit GEMM (unchanged, 64.6us measured)
// ============================================================
__constant__ int TAPD[9] = {0, 1, 2, 16, 17, 18, 32, 33, 34};

__global__ void __launch_bounds__(256)
conv_kernel()
{
    extern __shared__ uint32_t csm[];
    const uint32_t sb = smem_u32(csm);
    const int qx  = blockIdx.x;
    const int b   = blockIdx.y;
    const int tid = threadIdx.x;
    const int wz  = tid >> 5;
    const int lane = tid & 31;
    const int qm = lane >> 2, qk = lane & 3;

    int  ib[2][2];
    bool pv[2][2];
    #pragma unroll
    for (int t = 0; t < 2; t++) {
        #pragma unroll
        for (int h = 0; h < 2; h++) {
            int p = (wz * 2 + t) * 16 + qm + h * 8;
            bool v = p < HWSZ;
            int pr = v ? p / 14 : 0, pc = v ? p % 14 : 0;
            ib[t][h] = pr * 16 + pc;
            pv[t][h] = v;
        }
    }

    auto prefetch = [&](int ch, int pbuf) {
        const uint32_t xbuf = sb + (uint32_t)pbuf * (CV_STAGE_U32 * 4);
        const uint32_t wbuf = xbuf + CV_XS_U32 * 4;
        const int pg0 = qx * 256 + ch * 8;
        const int chg = qx * 32 + ch;
        #pragma unroll
        for (int q = tid; q < 512; q += 256) {
            int kp = q >> 6, j = q & 63;
            cp_async16(xbuf + (uint32_t)(kp * CV_XSTR + j * 4) * 4,
                       g_xph + ((size_t)(b * 1024 + pg0 + kp)) * 256 + j * 4);
        }
        for (int q = tid; q < 576; q += 256) {
            int tap = q / 64;
            int kp  = (q >> 3) & 7;
            int oq  = q & 7;
            cp_async16(wbuf + (uint32_t)(tap * CV_WTAP + kp * CV_WSTR + oq * 4) * 4,
                       g_wt2h + ((size_t)(chg * 9 + tap) * 8 + kp) * 32 + oq * 4);
        }
    };

    float acc[2][4][4];
    #pragma unroll
    for (int t = 0; t < 2; t++)
        #pragma unroll
        for (int n = 0; n < 4; n++)
            #pragma unroll
            for (int i = 0; i < 4; i++) acc[t][n][i] = 0.f;

    prefetch(0, 0);
    cp_commit();

    #pragma unroll 1
    for (int ch = 0; ch < 32; ch++) {
        if (ch + 1 < 32) {
            prefetch(ch + 1, (ch + 1) & 1);
            cp_commit();
            cp_wait<1>();
        } else {
            cp_wait<0>();
        }
        __syncthreads();

        const uint32_t* Xs = csm + (ch & 1) * CV_STAGE_U32;
        const uint32_t* Ws = Xs + CV_XS_U32;

        #pragma unroll
        for (int tap = 0; tap < 9; tap++) {
            const int d = TAPD[tap];
            uint32_t a[2][4];
            #pragma unroll
            for (int t = 0; t < 2; t++) {
                a[t][0] = Xs[qk * CV_XSTR + ib[t][0] + d];
                a[t][1] = Xs[qk * CV_XSTR + ib[t][1] + d];
                a[t][2] = Xs[(qk + 4) * CV_XSTR + ib[t][0] + d];
                a[t][3] = Xs[(qk + 4) * CV_XSTR + ib[t][1] + d];
            }
            #pragma unroll
            for (int nt = 0; nt < 4; nt++) {
                uint32_t bf[2];
                bf[0] = Ws[tap * CV_WTAP + qk * CV_WSTR + nt * 8 + qm];
                bf[1] = Ws[tap * CV_WTAP + (qk + 4) * CV_WSTR + nt * 8 + qm];
                mma_f16(acc[0][nt], a[0], bf);
                mma_f16(acc[1][nt], a[1], bf);
            }
        }
        __syncthreads();
    }

    float* dst = g_amp + ((size_t)qx * BB + b) * (HWSZ * COUT);
    #pragma unroll
    for (int t = 0; t < 2; t++) {
        #pragma unroll
        for (int h = 0; h < 2; h++) {
            if (!pv[t][h]) continue;
            int p = (wz * 2 + t) * 16 + qm + h * 8;
            #pragma unroll
            for (int nt = 0; nt < 4; nt++) {
                *(float2*)(dst + p * COUT + nt * 8 + 2 * qk) =
                    make_float2(acc[t][nt][h * 2], acc[t][nt][h * 2 + 1]);
            }
        }
    }
}

// ============================================================
// Kernel 1b: reduce conv partials + bias -> g_amh half2
// ============================================================
__global__ void __launch_bounds__(256)
amred_kernel(const float* __restrict__ bias)
{
    int idx = blockIdx.x * 256 + threadIdx.x;
    if (idx >= BB * COUT * 104) return;
    int j  = idx % 104;
    int bo = idx / 104;
    int o  = bo & 31;
    int b  = bo >> 5;
    const size_t QSTR = (size_t)BB * HWSZ * COUT;
    float s[2] = {0.f, 0.f};
    #pragma unroll
    for (int l = 0; l < 2; l++) {
        int p = 2 * j + l;
        if (p < HWSZ) {
            size_t e = (size_t)b * (HWSZ * COUT) + (size_t)p * COUT + o;
            s[l] = bias[o] + g_amp[e] + g_amp[e + QSTR] + g_amp[e + 2 * QSTR] + g_amp[e + 3 * QSTR];
        }
    }
    g_amh[idx] = pack_h2(s[0], s[1]);
}

// ============================================================
// Kernel 2: einsum via fp16 mma (unchanged)
// ============================================================
__global__ void __launch_bounds__(256)
einsum_kernel()
{
    extern __shared__ uint32_t esm[];
    const uint32_t sb = smem_u32(esm);

    const int mt  = blockIdx.x;
    const int b   = blockIdx.y;
    const int tid = threadIdx.x;
    const int wz  = tid >> 5;
    const int lane = tid & 31;
    const int qm = lane >> 2, qk = lane & 3;
    const int mh = wz >> 2, nt = wz & 3;
    const int i0 = mt * 128;

    for (int q = tid; q < 832; q += 256) {
        int row = q / 26, j = q % 26;
        cp_async16(sb + (uint32_t)(row * EM_STRU + j * 4) * 4,
                   g_amh + (size_t)(b * COUT + row) * 104 + j * 4);
    }

    auto prefetch_x = [&](int ch) {
        const uint32_t xbuf = sb + (uint32_t)((32 + 32 * (ch & 1)) * EM_STRU) * 4;
        for (int q = tid; q < 832; q += 256) {
            int row = q / 26, j = q % 26;
            cp_async16(xbuf + (uint32_t)(row * EM_STRU + j * 4) * 4,
                       g_xe + (size_t)(b * CIN + i0 + ch * 32 + row) * 104 + j * 4);
        }
    };

    prefetch_x(0);
    cp_commit();

    const float inv = 1.f / (float)HWSZ;

    #pragma unroll 1
    for (int ch = 0; ch < 4; ch++) {
        if (ch + 1 < 4) {
            prefetch_x(ch + 1);
            cp_commit();
            cp_wait<1>();
        } else {
            cp_wait<0>();
        }
        __syncthreads();

        const int arow0 = (32 + 32 * (ch & 1) + mh * 16 + qm) * EM_STRU;
        const int brow0 = (nt * 8 + qm) * EM_STRU;

        float acc[4] = {0.f, 0.f, 0.f, 0.f};
        #pragma unroll
        for (int ks = 0; ks < 13; ks++) {
            const int k0 = ks * 8;
            uint32_t a[4], bf[2];
            a[0] = esm[arow0 + k0 + qk];
            a[1] = esm[arow0 + 8 * EM_STRU + k0 + qk];
            a[2] = esm[arow0 + k0 + 4 + qk];
            a[3] = esm[arow0 + 8 * EM_STRU + k0 + 4 + qk];
            bf[0] = esm[brow0 + k0 + qk];
            bf[1] = esm[brow0 + k0 + 4 + qk];
            mma_f16(acc, a, bf);
        }

        int i = i0 + ch * 32 + mh * 16 + qm;
        int o = nt * 8 + 2 * qk;
        float* d0 = g_feat + (size_t)b * FEAT + (size_t)i * COUT + o;
        *(float2*)d0 = make_float2(rna_tf32(acc[0] * inv), rna_tf32(acc[1] * inv));
        float* d1 = d0 + 8 * COUT;
        *(float2*)d1 = make_float2(rna_tf32(acc[2] * inv), rna_tf32(acc[3] * inv));
        __syncthreads();
    }
}

// ============================================================
// Kernel 3: fc6 partials, tf32 mma, 4-stage cp.async pipeline.
// grid (8, 32), block 256, 2 CTAs/SM. Chunk K=32, 64 chunks.
// ============================================================
__global__ void __launch_bounds__(256, 2)
fc6_kernel(const float* __restrict__ w6)
{
    extern __shared__ float fsm[];
    const uint32_t sb = smem_u32(fsm);

    const int mt  = blockIdx.x;
    const int kt  = blockIdx.y;
    const int tid = threadIdx.x;
    const int wz  = tid >> 5;
    const int lane = tid & 31;
    const int qm = lane >> 2, qk = lane & 3;

    const int    mbase = mt * 128;
    const size_t kbase = (size_t)kt * FC6_KPER;

    const int arow = tid >> 1, akoff = (tid & 1) * 16;
    const int brow = tid >> 2, bkoff = (tid & 3) * 8;
    const float* ga0 = w6 + (size_t)(mbase + arow) * FEAT + kbase + akoff;
    const float* gb0 = g_feat + (size_t)brow * FEAT + kbase + bkoff;

    auto prefetch = [&](int ch) {
        const int st = ch & 3;
        const uint32_t abuf = sb + (uint32_t)st * (STAGE_FLOATS * 4);
        const uint32_t bbuf = abuf + A_FLOATS * 4;
        const float* ga = ga0 + (size_t)ch * FC6_KC;
        const uint32_t adst = abuf + (uint32_t)(arow * F6_STR + akoff) * 4;
        #pragma unroll
        for (int j = 0; j < 4; j++)
            cp_async16(adst + j * 16, ga + j * 4);
        const float* gb = gb0 + (size_t)ch * FC6_KC;
        const uint32_t bdst = bbuf + (uint32_t)(brow * F6_STR + bkoff) * 4;
        #pragma unroll
        for (int j = 0; j < 2; j++)
            cp_async16(bdst + j * 16, gb + j * 4);
    };

    float acc[8][4];
    #pragma unroll
    for (int j = 0; j < 8; j++)
        #pragma unroll
        for (int r = 0; r < 4; r++) acc[j][r] = 0.f;

    prefetch(0); cp_commit();
    prefetch(1); cp_commit();
    prefetch(2); cp_commit();

    #pragma unroll 1
    for (int ch = 0; ch < FC6_NCHUNK; ch++) {
        if (ch + 3 < FC6_NCHUNK) {
            prefetch(ch + 3);           // overwrites stage (ch-1)&3: synced last iter
            cp_commit();
            cp_wait<3>();
        } else if (ch + 2 < FC6_NCHUNK) {
            cp_wait<2>();
        } else if (ch + 1 < FC6_NCHUNK) {
            cp_wait<1>();
        } else {
            cp_wait<0>();
        }
        __syncthreads();

        const float* As = fsm + (ch & 3) * STAGE_FLOATS;
        const uint32_t* Au = (const uint32_t*)As;
        const uint32_t* Bu = Au + A_FLOATS;
        const int m0 = wz * 16;

        #pragma unroll
        for (int ks = 0; ks < 4; ks++) {
            const int k0 = ks * 8;
            uint32_t a[4];
            a[0] = rna_u(Au[(m0 + qm) * F6_STR + k0 + qk]);
            a[1] = rna_u(Au[(m0 + qm + 8) * F6_STR + k0 + qk]);
            a[2] = rna_u(Au[(m0 + qm) * F6_STR + k0 + 4 + qk]);
            a[3] = rna_u(Au[(m0 + qm + 8) * F6_STR + k0 + 4 + qk]);
            #pragma unroll
            for (int nt = 0; nt < 8; nt++) {
                uint32_t bf[2];
                bf[0] = Bu[(nt * 8 + qm) * F6_STR + k0 + qk];
                bf[1] = Bu[(nt * 8 + qm) * F6_STR + k0 + 4 + qk];
                mma_tf32(acc[nt], a, bf);
            }
        }
        __syncthreads();
    }

    const int r = mbase + wz * 16 + qm;
    #pragma unroll
    for (int nt = 0; nt < 8; nt++) {
        int bcol = nt * 8 + 2 * qk;
        *(float2*)(g_p6 + ((size_t)kt * REP + r) * BB + bcol) =
            make_float2(acc[nt][0], acc[nt][1]);
        *(float2*)(g_p6 + ((size_t)kt * REP + r + 8) * BB + bcol) =
            make_float2(acc[nt][2], acc[nt][3]);
    }
}

// ============================================================
// Kernel 4: reduce fc6 partials + bias + relu -> g_h6
// ============================================================
__global__ void __launch_bounds__(256)
reduce6_kernel(const float* __restrict__ b6)
{
    int idx = blockIdx.x * 256 + threadIdx.x;
    int r = idx >> 6, b = idx & 63;
    float sum = b6[r];
    #pragma unroll 8
    for (int kt = 0; kt < FC6_KT; kt++)
        sum += g_p6[((size_t)kt * REP + r) * BB + b];
    g_h6[(size_t)b * REP + r] = fmaxf(sum, 0.f);
}

// ============================================================
// Kernel 5: fc7 + bias + relu. grid (16 bgroups, 4 r-quarters).
// ============================================================
__global__ void __launch_bounds__(256)
fc7_kernel(const float* __restrict__ w7, const float* __restrict__ b7,
           float* __restrict__ out)
{
    const int b0 = blockIdx.x * 4;
    const int r  = blockIdx.y * 256 + threadIdx.x;
    const int tid = threadIdx.x;

    __shared__ float hs[4][REP];
    for (int t = tid; t < 4 * REP; t += 256)
        hs[t >> 10][t & 1023] = g_h6[(size_t)(b0 + (t >> 10)) * REP + (t & 1023)];
    __syncthreads();

    const float4* wr = (const float4*)(w7 + (size_t)r * REP);
    float s0 = 0.f, s1 = 0.f, s2 = 0.f, s3 = 0.f;
    #pragma unroll 4
    for (int k4 = 0; k4 < REP / 4; k4++) {
        float4 wv = wr[k4];
        float4 h0 = *(const float4*)&hs[0][k4 * 4];
        float4 h1 = *(const float4*)&hs[1][k4 * 4];
        float4 h2 = *(const float4*)&hs[2][k4 * 4];
        float4 h3 = *(const float4*)&hs[3][k4 * 4];
        s0 += wv.x * h0.x + wv.y * h0.y + wv.z * h0.z + wv.w * h0.w;
        s1 += wv.x * h1.x + wv.y * h1.y + wv.z * h1.z + wv.w * h1.w;
        s2 += wv.x * h2.x + wv.y * h2.y + wv.z * h2.z + wv.w * h2.w;
        s3 += wv.x * h3.x + wv.y * h3.y + wv.z * h3.z + wv.w * h3.w;
    }
    float bv = b7[r];
    out[(size_t)(b0 + 0) * REP + r] = fmaxf(s0 + bv, 0.f);
    out[(size_t)(b0 + 1) * REP + r] = fmaxf(s1 + bv, 0.f);
    out[(size_t)(b0 + 2) * REP + r] = fmaxf(s2 + bv, 0.f);
    out[(size_t)(b0 + 3) * REP + r] = fmaxf(s3 + bv, 0.f);
}

// ============================================================
// launch
// ============================================================
extern "C" void kernel_launch(void* const* d_in, const int* in_sizes, int n_in,
                              void* d_out, int out_size)
{
    const float* x      = (const float*)d_in[0];
    const float* conv_w = (const float*)d_in[1];
    const float* conv_b = (const float*)d_in[2];
    const float* w6     = (const float*)d_in[3];
    const float* b6     = (const float*)d_in[4];
    const float* w7     = (const float*)d_in[5];
    const float* b7     = (const float*)d_in[6];
    float* out = (float*)d_out;

    cudaFuncSetAttribute(conv_kernel,   cudaFuncAttributeMaxDynamicSharedMemorySize, CONV_SMEM);
    cudaFuncSetAttribute(einsum_kernel, cudaFuncAttributeMaxDynamicSharedMemorySize, EM_SMEM);
    cudaFuncSetAttribute(fc6_kernel,    cudaFuncAttributeMaxDynamicSharedMemorySize, FC6_SMEM);

    size_t nxc = (size_t)BB * 1024 * 256;
    size_t nxe = (size_t)BB * CIN * 104;
    xpad_conv_kernel<<<dim3((unsigned)((nxc + 255) / 256)), 256>>>(x);
    xpad_eins_kernel<<<dim3((unsigned)((nxe + 255) / 256)), 256>>>(x);
    wtrans_kernel   <<<dim3((128 * 9 * 8 * 32 + 255) / 256), 256>>>(conv_w);
    conv_kernel     <<<dim3(4, BB),  256, CONV_SMEM>>>();
    amred_kernel    <<<dim3((BB * COUT * 104 + 255) / 256), 256>>>(conv_b);
    einsum_kernel   <<<dim3(16, BB), 256, EM_SMEM>>>();
    fc6_kernel      <<<dim3(8, FC6_KT), 256, FC6_SMEM>>>(w6);
    reduce6_kernel  <<<dim3(BB * REP / 256), 256>>>(b6);
    fc7_kernel      <<<dim3(16, 4), 256>>>(w7, b7, out);
}